// round 7
// baseline (speedup 1.0000x reference)
#include <cuda_runtime.h>
#include <cuda.h>
#include <cstdint>

#define NMAX 50000
#define RK 300
#define TILE 256

__device__ float g_h[NMAX * 64];
__device__ float g_agg[NMAX * 64];
__device__ float2 g_fw1frag[10 * 4 * 8 * 32];  // [c][s][t][lane] -> (b0,b1)
__device__ float2 g_fw2frag[8 * 8 * 32];       // [s][t][lane]
__device__ int g_is64;

__device__ __forceinline__ float sspf(float x) {
    float t = __expf(-fabsf(x));
    return fmaxf(x, 0.f) + __logf(1.f + t) - 0.69314718055994531f;
}
__device__ __forceinline__ uint32_t cvt_tf32(float x) {
    uint32_t r; asm("cvt.rna.tf32.f32 %0, %1;" : "=r"(r) : "f"(x)); return r;
}
__device__ __forceinline__ float tf32r(float x) { return __uint_as_float(cvt_tf32(x)); }

__device__ __forceinline__ void mma_tf32(float d[4], uint32_t a0, uint32_t a1,
                                         uint32_t a2, uint32_t a3,
                                         uint32_t b0, uint32_t b1) {
    asm volatile(
        "mma.sync.aligned.m16n8k8.row.col.f32.tf32.tf32.f32 "
        "{%0,%1,%2,%3}, {%4,%5,%6,%7}, {%8,%9}, {%0,%1,%2,%3};"
        : "+f"(d[0]), "+f"(d[1]), "+f"(d[2]), "+f"(d[3])
        : "r"(a0), "r"(a1), "r"(a2), "r"(a3), "r"(b0), "r"(b1));
}
__device__ __forceinline__ void cp16(uint32_t saddr, const void* g, int sz) {
    asm volatile("cp.async.cg.shared.global [%0], [%1], 16, %2;"
                 :: "r"(saddr), "l"(g), "r"(sz));
}
__device__ __forceinline__ void cp_commit() { asm volatile("cp.async.commit_group;"); }
__device__ __forceinline__ void cp_wait0()  { asm volatile("cp.async.wait_group 0;"); }

__device__ __forceinline__ void tma2d(uint32_t dst, const void* map, int x, int y,
                                      uint32_t mbar) {
    asm volatile(
        "cp.async.bulk.tensor.2d.shared::cta.global.tile.mbarrier::complete_tx::bytes "
        "[%0], [%1, {%2, %3}], [%4];"
        :: "r"(dst), "l"(map), "r"(x), "r"(y), "r"(mbar) : "memory");
}
__device__ __forceinline__ void mbar_init(uint32_t a, uint32_t cnt) {
    asm volatile("mbarrier.init.shared.b64 [%0], %1;" :: "r"(a), "r"(cnt) : "memory");
}
__device__ __forceinline__ void mbar_expect(uint32_t a, uint32_t tx) {
    asm volatile("mbarrier.arrive.expect_tx.shared.b64 _, [%0], %1;"
                 :: "r"(a), "r"(tx) : "memory");
}
__device__ __forceinline__ void mbar_arrive(uint32_t a) {
    asm volatile("mbarrier.arrive.shared.b64 _, [%0];" :: "r"(a) : "memory");
}
__device__ __forceinline__ void mbar_wait(uint32_t a, uint32_t ph) {
    uint32_t done = 0;
    do {
        asm volatile(
            "{\n\t.reg .pred p;\n\t"
            "mbarrier.try_wait.parity.acquire.cta.shared::cta.b64 p, [%1], %2, 0x989680;\n\t"
            "selp.b32 %0, 1, 0, p;\n\t}"
            : "=r"(done) : "r"(a), "r"(ph) : "memory");
    } while (!done);
}

__global__ void detect_idx_kernel(const int* __restrict__ ei32) {
    if (threadIdx.x == 0 && blockIdx.x == 0) {
        int ornz = 0;
#pragma unroll
        for (int i = 0; i < 64; ++i) ornz |= ei32[2 * i + 1];
        g_is64 = (ornz == 0) ? 1 : 0;
    }
}

// fragment-major tf32 weights. fw1: k = c*32 + 8s + t4 (+4 for b1), n = 8t + g4
__global__ void prep_frag_kernel(const float* __restrict__ fw1,
                                 const float* __restrict__ fw2) {
    int i = blockIdx.x * blockDim.x + threadIdx.x;
    if (i < 10 * 4 * 8 * 32) {
        int lane = i & 31, t = (i >> 5) & 7, s = (i >> 8) & 3, c = i >> 10;
        int t4 = lane & 3, g4 = lane >> 2;
        int k = c * 32 + 8 * s + t4, n = 8 * t + g4;
        float b0 = (k < RK) ? tf32r(fw1[k * 64 + n]) : 0.f;
        float b1 = (k + 4 < RK) ? tf32r(fw1[(k + 4) * 64 + n]) : 0.f;
        g_fw1frag[i] = make_float2(b0, b1);
    }
    if (i < 8 * 8 * 32) {
        int lane = i & 31, t = (i >> 5) & 7, s = i >> 8;
        int t4 = lane & 3, g4 = lane >> 2;
        int k = 8 * s + t4, n = 8 * t + g4;
        g_fw2frag[i] = make_float2(tf32r(fw2[k * 64 + n]), tf32r(fw2[(k + 4) * 64 + n]));
    }
}

// ---------------------------------------------------------------------------
// node_pre: h = x @ l1w + l1b, and zero g_agg. 128 nodes/block, 2 barriers.
// ---------------------------------------------------------------------------
__global__ void __launch_bounds__(256)
node_pre_kernel(const float* __restrict__ x, const float* __restrict__ W,
                const float* __restrict__ b, int N) {
    __shared__ float xs[128 * 64];
    int tid = threadIdx.x;
    int j = tid & 63, q = tid >> 6;
    long n0 = (long)blockIdx.x * 128;
    uint32_t sb = (uint32_t)__cvta_generic_to_shared(xs);
    for (int i = tid; i < 2048; i += 256) {
        long node = n0 + (i >> 4);
        cp16(sb + i * 16, x + node * 64 + (i & 15) * 4, node < N ? 16 : 0);
    }
    cp_commit();
    float Wc[64];
#pragma unroll
    for (int k = 0; k < 64; ++k) Wc[k] = W[k * 64 + j];
    float bj = b[j];
    cp_wait0();
    __syncthreads();
#pragma unroll 4
    for (int nn = 0; nn < 32; ++nn) {
        int r = nn * 4 + q;
        long node = n0 + r;
        float acc = bj;
        const float* xr = xs + r * 64;
#pragma unroll
        for (int k = 0; k < 64; k += 4) {
            float4 xv = *(const float4*)(xr + k);
            acc += xv.x * Wc[k] + xv.y * Wc[k + 1] + xv.z * Wc[k + 2] + xv.w * Wc[k + 3];
        }
        if (node < N) {
            g_h[node * 64 + j] = acc;
            g_agg[node * 64 + j] = 0.f;
        }
    }
}

// ---------------------------------------------------------------------------
// node_post: out = ssp(agg @ l2w + l2b) @ l3w + l3b + x0. 128 nodes/block.
// ---------------------------------------------------------------------------
__global__ void __launch_bounds__(256)
node_post_kernel(const float* __restrict__ x0, const float* __restrict__ W2,
                 const float* __restrict__ b2, const float* __restrict__ W3,
                 const float* __restrict__ b3, float* __restrict__ out, int N) {
    extern __shared__ float smp[];
    float* xs = smp;            // 128*64
    float* ts = smp + 8192;     // 128*64
    int tid = threadIdx.x;
    int j = tid & 63, q = tid >> 6;
    long n0 = (long)blockIdx.x * 128;
    uint32_t sb = (uint32_t)__cvta_generic_to_shared(xs);
    for (int i = tid; i < 2048; i += 256) {
        long node = n0 + (i >> 4);
        cp16(sb + i * 16, g_agg + node * 64 + (i & 15) * 4, node < N ? 16 : 0);
    }
    cp_commit();
    float W2c[64], W3c[64];
#pragma unroll
    for (int k = 0; k < 64; ++k) { W2c[k] = W2[k * 64 + j]; W3c[k] = W3[k * 64 + j]; }
    float b2j = b2[j], b3j = b3[j];
    cp_wait0();
    __syncthreads();
#pragma unroll 4
    for (int nn = 0; nn < 32; ++nn) {
        int r = nn * 4 + q;
        float acc = b2j;
        const float* xr = xs + r * 64;
#pragma unroll
        for (int k = 0; k < 64; k += 4) {
            float4 xv = *(const float4*)(xr + k);
            acc += xv.x * W2c[k] + xv.y * W2c[k + 1] + xv.z * W2c[k + 2] + xv.w * W2c[k + 3];
        }
        ts[r * 64 + j] = sspf(acc);
    }
    __syncthreads();
#pragma unroll 4
    for (int nn = 0; nn < 32; ++nn) {
        int r = nn * 4 + q;
        long node = n0 + r;
        float acc = b3j;
        const float* tr = ts + r * 64;
#pragma unroll
        for (int k = 0; k < 64; k += 4) {
            float4 tv = *(const float4*)(tr + k);
            acc += tv.x * W3c[k] + tv.y * W3c[k + 1] + tv.z * W3c[k + 2] + tv.w * W3c[k + 3];
        }
        if (node < N) out[node * 64 + j] = acc + x0[node * 64 + j];
    }
}

// ---------------------------------------------------------------------------
// edge kernel: persistent, TMA + full/empty mbarrier pipeline (no per-chunk
// CTA barriers -> warps drift), resident fragment weights, shuffle handoff.
// ---------------------------------------------------------------------------
#define OFF_A   0        // 2 bufs x 256 rows x 32 cols = 16384 (64KB)
#define OFF_FW1 16384    // 10240 float2 = 20480 floats (80KB)
#define OFF_FW2 36864    // 2048 float2 = 4096 floats (16KB)
#define OFF_C   40960    // 256 x 64 = 16384 (64KB)
#define OFF_B1  57344
#define OFF_B2  57408
#define OFF_MB  57472    // 4 mbarriers: full0, full1, empty0, empty1
#define SMEM_FLOATS 57480
#define CSW(r, c) ((r) * 64 + ((c) ^ (((r) & 7) << 2)))

__global__ void __launch_bounds__(512, 1)
edge_kernel(const __grid_constant__ CUtensorMap tmap, const void* __restrict__ ei,
            const float* __restrict__ dist, const float* __restrict__ cutoff,
            const float* __restrict__ fb1, const float* __restrict__ fb2,
            int E, int NT, int GRIDSZ) {
    extern __shared__ __align__(1024) float sm[];
    uint32_t sbase = (uint32_t)__cvta_generic_to_shared(sm);
    int tid = threadIdx.x, lane = tid & 31, warp = tid >> 5;
    int t4 = lane & 3, g4 = lane >> 2, rw = warp * 16;
    const float2* FW1 = (const float2*)(sm + OFF_FW1);
    const float2* FW2 = (const float2*)(sm + OFF_FW2);
    uint32_t fullb[2]  = {sbase + OFF_MB * 4,      sbase + OFF_MB * 4 + 8};
    uint32_t emptyb[2] = {sbase + OFF_MB * 4 + 16, sbase + OFF_MB * 4 + 24};

    for (int i = tid; i < 5120; i += 512)
        cp16(sbase + (OFF_FW1 + i * 4) * 4, (const char*)g_fw1frag + i * 16, 16);
    for (int i = tid; i < 1024; i += 512)
        cp16(sbase + (OFF_FW2 + i * 4) * 4, (const char*)g_fw2frag + i * 16, 16);
    cp_commit();
    if (tid < 64) { sm[OFF_B1 + tid] = fb1[tid]; sm[OFF_B2 + tid] = fb2[tid]; }
    if (tid == 0) {
        mbar_init(fullb[0], 1);  mbar_init(fullb[1], 1);
        mbar_init(emptyb[0], 16); mbar_init(emptyb[1], 16);
    }
    cp_wait0();
    asm volatile("fence.proxy.async.shared::cta;" ::: "memory");
    __syncthreads();

    int is64 = g_is64;
    float picf = 3.14159265f / (*cutoff);

    auto issue = [&](long t, int c, int b) {
        if (t >= (long)NT) return;
        mbar_expect(fullb[b], 32768u);
        tma2d(sbase + (OFF_A + b * 8192) * 4, (const void*)&tmap,
              c * 32, (int)(t * TILE), fullb[b]);
    };

    long tile = blockIdx.x;
    if (tid == 0) { issue(tile, 0, 0); issue(tile, 1, 1); }
    int fp0 = 0, fp1 = 0, ep0 = 0, ep1 = 0;

    int el = tid >> 1, half = tid & 1;
    int u = t4 >> 1, p = t4 & 1;
    int l1 = 4 * g4 + u, l2 = l1 + 2;

    for (; tile < (long)NT; tile += GRIDSZ) {
        long e0 = tile * TILE;

        // preload epilogue indices/dist early (hide L2 latency behind GEMM1)
        long e = e0 + el;
        long long dstn = 0, srcn = 0;
        float f = 0.f;
        if (e < (long)E) {
            if (is64) {
                const long long* pp = (const long long*)ei;
                dstn = pp[e]; srcn = pp[(long)E + e];
            } else {
                const int* pp = (const int*)ei;
                dstn = pp[e]; srcn = pp[(long)E + e];
            }
            dstn = dstn < 0 ? 0 : (dstn >= NMAX ? NMAX - 1 : dstn);
            srcn = srcn < 0 ? 0 : (srcn >= NMAX ? NMAX - 1 : srcn);
            f = 1.f + __cosf(picf * dist[e]);
        }

        float acc[8][4];
#pragma unroll
        for (int t = 0; t < 8; ++t)
#pragma unroll
            for (int jj = 0; jj < 4; ++jj) acc[t][jj] = 0.f;

#pragma unroll 1
        for (int c = 0; c < 10; ++c) {
            int b = c & 1;
            if (b) { mbar_wait(fullb[1], fp1); fp1 ^= 1; }
            else   { mbar_wait(fullb[0], fp0); fp0 ^= 1; }
            const float* A = sm + OFF_A + b * 8192;
            int r0 = rw + g4, r1 = r0 + 8;
            int sw = g4 << 2;
#pragma unroll
            for (int s = 0; s < 4; ++s) {
                int w0 = 8 * s + t4;
                uint32_t a0 = cvt_tf32(A[r0 * 32 + (w0 ^ sw)]);
                uint32_t a1 = cvt_tf32(A[r1 * 32 + (w0 ^ sw)]);
                uint32_t a2 = cvt_tf32(A[r0 * 32 + ((w0 + 4) ^ sw)]);
                uint32_t a3 = cvt_tf32(A[r1 * 32 + ((w0 + 4) ^ sw)]);
#pragma unroll
                for (int t = 0; t < 8; ++t) {
                    float2 bb = FW1[((c * 4 + s) * 8 + t) * 32 + lane];
                    mma_tf32(acc[t], a0, a1, a2, a3,
                             __float_as_uint(bb.x), __float_as_uint(bb.y));
                }
            }
            // consumer done with buffer b for this chunk
            __syncwarp();
            if (lane == 0) mbar_arrive(b ? emptyb[1] : emptyb[0]);
            // producer: wait for drain, then refill with next chunk
            if (tid == 0) {
                if (b) { mbar_wait(emptyb[1], ep1); ep1 ^= 1; }
                else   { mbar_wait(emptyb[0], ep0); ep0 ^= 1; }
                if (c < 8) issue(tile, c + 2, b);
                else issue(tile + GRIDSZ, c - 8, b);
            }
        }

        // bias + ssp in-place on acc
#pragma unroll
        for (int t = 0; t < 8; ++t) {
            int cb = 8 * t + 2 * t4;
            float b0v = sm[OFF_B1 + cb], b1v = sm[OFF_B1 + cb + 1];
            acc[t][0] = sspf(acc[t][0] + b0v);
            acc[t][1] = sspf(acc[t][1] + b1v);
            acc[t][2] = sspf(acc[t][2] + b0v);
            acc[t][3] = sspf(acc[t][3] + b1v);
        }

        // GEMM2 with A-fragments gathered via warp shuffles
        float acc2[8][4];
#pragma unroll
        for (int t = 0; t < 8; ++t)
#pragma unroll
            for (int jj = 0; jj < 4; ++jj) acc2[t][jj] = 0.f;
#pragma unroll
        for (int s = 0; s < 8; ++s) {
            float v00 = __shfl_sync(0xffffffffu, acc[s][0], l1);
            float v01 = __shfl_sync(0xffffffffu, acc[s][1], l1);
            float v10 = __shfl_sync(0xffffffffu, acc[s][2], l1);
            float v11 = __shfl_sync(0xffffffffu, acc[s][3], l1);
            float w00 = __shfl_sync(0xffffffffu, acc[s][0], l2);
            float w01 = __shfl_sync(0xffffffffu, acc[s][1], l2);
            float w10 = __shfl_sync(0xffffffffu, acc[s][2], l2);
            float w11 = __shfl_sync(0xffffffffu, acc[s][3], l2);
            uint32_t a0 = cvt_tf32(p ? v01 : v00);
            uint32_t a1 = cvt_tf32(p ? v11 : v10);
            uint32_t a2 = cvt_tf32(p ? w01 : w00);
            uint32_t a3 = cvt_tf32(p ? w11 : w10);
#pragma unroll
            for (int t = 0; t < 8; ++t) {
                float2 bb = FW2[(s * 8 + t) * 32 + lane];
                mma_tf32(acc2[t], a0, a1, a2, a3,
                         __float_as_uint(bb.x), __float_as_uint(bb.y));
            }
        }

        // bias + ssp -> C (for per-edge epilogue access)
#pragma unroll
        for (int t = 0; t < 8; ++t) {
            int cb = 8 * t + 2 * t4;
            float b0v = sm[OFF_B2 + cb], b1v = sm[OFF_B2 + cb + 1];
            *(float2*)&sm[OFF_C + CSW(rw + g4, cb)] =
                make_float2(sspf(acc2[t][0] + b0v), sspf(acc2[t][1] + b1v));
            *(float2*)&sm[OFF_C + CSW(rw + g4 + 8, cb)] =
                make_float2(sspf(acc2[t][2] + b0v), sspf(acc2[t][3] + b1v));
        }
        __syncthreads();

        // epilogue: gather h[src], scatter atomics into agg[dst]
        if (e < (long)E) {
            const float* hrow = g_h + (long)srcn * 64 + half * 32;
            float* arow = g_agg + (long)dstn * 64 + half * 32;
#pragma unroll
            for (int jj = 0; jj < 8; ++jj) {
                float4 w = *(const float4*)&sm[OFF_C + CSW(el, half * 32 + 4 * jj)];
                float4 h4 = *(const float4*)(hrow + 4 * jj);
                atomicAdd((float4*)(arow + 4 * jj),
                          make_float4(w.x * h4.x * f, w.y * h4.y * f,
                                      w.z * h4.z * f, w.w * h4.w * f));
            }
        }
        __syncthreads();
    }
}

// ---------------------------------------------------------------------------
typedef CUresult (*PFN_tmencode)(
    CUtensorMap*, CUtensorMapDataType, cuuint32_t, void*,
    const cuuint64_t*, const cuuint64_t*, const cuuint32_t*, const cuuint32_t*,
    CUtensorMapInterleave, CUtensorMapSwizzle, CUtensorMapL2promotion,
    CUtensorMapFloatOOBfill);

extern "C" void kernel_launch(void* const* d_in, const int* in_sizes, int n_in,
                              void* d_out, int out_size) {
    const void* ei       = d_in[0];
    const float* x       = (const float*)d_in[1];
    const float* rbf     = (const float*)d_in[2];
    const float* dist    = (const float*)d_in[3];
    const float* cutoff  = (const float*)d_in[4];
    const float* fw1     = (const float*)d_in[5];
    const float* fb1     = (const float*)d_in[6];
    const float* fw2     = (const float*)d_in[7];
    const float* fb2     = (const float*)d_in[8];
    const float* l1w     = (const float*)d_in[9];
    const float* l1b     = (const float*)d_in[10];
    const float* l2w     = (const float*)d_in[11];
    const float* l2b     = (const float*)d_in[12];
    const float* l3w     = (const float*)d_in[13];
    const float* l3b     = (const float*)d_in[14];

    int E = in_sizes[0] / 2;
    int N = in_sizes[1] / 64;
    int NT = (E + TILE - 1) / TILE;
    int NB = (N + 127) / 128;

    static PFN_tmencode enc = nullptr;
    if (!enc) {
        cudaDriverEntryPointQueryResult st;
        cudaGetDriverEntryPointByVersion("cuTensorMapEncodeTiled", (void**)&enc,
                                         12000, cudaEnableDefault, &st);
    }
    alignas(64) CUtensorMap tmap;
    {
        cuuint64_t dims[2]    = {(cuuint64_t)RK, (cuuint64_t)E};
        cuuint64_t strides[1] = {(cuuint64_t)RK * 4};
        cuuint32_t box[2]     = {32, TILE};
        cuuint32_t estr[2]    = {1, 1};
        enc(&tmap, CU_TENSOR_MAP_DATA_TYPE_FLOAT32, 2, (void*)rbf,
            dims, strides, box, estr,
            CU_TENSOR_MAP_INTERLEAVE_NONE, CU_TENSOR_MAP_SWIZZLE_128B,
            CU_TENSOR_MAP_L2_PROMOTION_L2_128B, CU_TENSOR_MAP_FLOAT_OOB_FILL_NONE);
    }

    static int sms = 0;
    if (!sms) cudaDeviceGetAttribute(&sms, cudaDevAttrMultiProcessorCount, 0);
    int grid = sms > 0 ? sms : 148;

    cudaFuncSetAttribute(edge_kernel, cudaFuncAttributeMaxDynamicSharedMemorySize,
                         SMEM_FLOATS * 4);
    cudaFuncSetAttribute(node_post_kernel, cudaFuncAttributeMaxDynamicSharedMemorySize,
                         65536);

    detect_idx_kernel<<<1, 32>>>((const int*)ei);
    prep_frag_kernel<<<(10 * 4 * 8 * 32 + 255) / 256, 256>>>(fw1, fw2);
    node_pre_kernel<<<NB, 256>>>(x, l1w, l1b, N);
    edge_kernel<<<grid, 512, SMEM_FLOATS * 4>>>(tmap, ei, dist, cutoff,
                                                fb1, fb2, E, NT, grid);
    node_post_kernel<<<NB, 256, 65536>>>(x, l2w, l2b, l3w, l3b, (float*)d_out, N);
}

// round 8
// speedup vs baseline: 1.0006x; 1.0006x over previous
#include <cuda_runtime.h>
#include <cuda.h>
#include <cstdint>

#define NMAX 50000
#define RK 300
#define TILE 256

__device__ float g_h[NMAX * 64];
__device__ float g_agg[NMAX * 64];
__device__ float2 g_fw1frag[10 * 4 * 8 * 32];  // [c][s][t][lane] -> (b0,b1)
__device__ float2 g_fw2frag[8 * 8 * 32];       // [s][t][lane]
__device__ int g_is64;

__device__ __forceinline__ float sspf(float x) {
    float t = __expf(-fabsf(x));
    return fmaxf(x, 0.f) + __logf(1.f + t) - 0.69314718055994531f;
}
__device__ __forceinline__ uint32_t cvt_tf32(float x) {
    uint32_t r; asm("cvt.rna.tf32.f32 %0, %1;" : "=r"(r) : "f"(x)); return r;
}
__device__ __forceinline__ float tf32r(float x) { return __uint_as_float(cvt_tf32(x)); }

__device__ __forceinline__ void mma_tf32(float d[4], uint32_t a0, uint32_t a1,
                                         uint32_t a2, uint32_t a3,
                                         uint32_t b0, uint32_t b1) {
    asm volatile(
        "mma.sync.aligned.m16n8k8.row.col.f32.tf32.tf32.f32 "
        "{%0,%1,%2,%3}, {%4,%5,%6,%7}, {%8,%9}, {%0,%1,%2,%3};"
        : "+f"(d[0]), "+f"(d[1]), "+f"(d[2]), "+f"(d[3])
        : "r"(a0), "r"(a1), "r"(a2), "r"(a3), "r"(b0), "r"(b1));
}
__device__ __forceinline__ void cp16(uint32_t saddr, const void* g, int sz) {
    asm volatile("cp.async.cg.shared.global [%0], [%1], 16, %2;"
                 :: "r"(saddr), "l"(g), "r"(sz));
}
__device__ __forceinline__ void cp_commit() { asm volatile("cp.async.commit_group;"); }
__device__ __forceinline__ void cp_wait0()  { asm volatile("cp.async.wait_group 0;"); }

__device__ __forceinline__ void tma2d(uint32_t dst, const void* map, int x, int y,
                                      uint32_t mbar) {
    asm volatile(
        "cp.async.bulk.tensor.2d.shared::cta.global.tile.mbarrier::complete_tx::bytes "
        "[%0], [%1, {%2, %3}], [%4];"
        :: "r"(dst), "l"(map), "r"(x), "r"(y), "r"(mbar) : "memory");
}
__device__ __forceinline__ void mbar_init(uint32_t a, uint32_t cnt) {
    asm volatile("mbarrier.init.shared.b64 [%0], %1;" :: "r"(a), "r"(cnt) : "memory");
}
__device__ __forceinline__ void mbar_expect(uint32_t a, uint32_t tx) {
    asm volatile("mbarrier.arrive.expect_tx.shared.b64 _, [%0], %1;"
                 :: "r"(a), "r"(tx) : "memory");
}
__device__ __forceinline__ void mbar_arrive(uint32_t a) {
    asm volatile("mbarrier.arrive.shared.b64 _, [%0];" :: "r"(a) : "memory");
}
__device__ __forceinline__ void mbar_wait(uint32_t a, uint32_t ph) {
    uint32_t done = 0;
    do {
        asm volatile(
            "{\n\t.reg .pred p;\n\t"
            "mbarrier.try_wait.parity.acquire.cta.shared::cta.b64 p, [%1], %2, 0x989680;\n\t"
            "selp.b32 %0, 1, 0, p;\n\t}"
            : "=r"(done) : "r"(a), "r"(ph) : "memory");
    } while (!done);
}

__global__ void detect_idx_kernel(const int* __restrict__ ei32) {
    if (threadIdx.x == 0 && blockIdx.x == 0) {
        int ornz = 0;
#pragma unroll
        for (int i = 0; i < 64; ++i) ornz |= ei32[2 * i + 1];
        g_is64 = (ornz == 0) ? 1 : 0;
    }
}

// fragment-major tf32 weights. fw1: k = c*32 + 8s + t4 (+4 for b1), n = 8t + g4
__global__ void prep_frag_kernel(const float* __restrict__ fw1,
                                 const float* __restrict__ fw2) {
    int i = blockIdx.x * blockDim.x + threadIdx.x;
    if (i < 10 * 4 * 8 * 32) {
        int lane = i & 31, t = (i >> 5) & 7, s = (i >> 8) & 3, c = i >> 10;
        int t4 = lane & 3, g4 = lane >> 2;
        int k = c * 32 + 8 * s + t4, n = 8 * t + g4;
        float b0 = (k < RK) ? tf32r(fw1[k * 64 + n]) : 0.f;
        float b1 = (k + 4 < RK) ? tf32r(fw1[(k + 4) * 64 + n]) : 0.f;
        g_fw1frag[i] = make_float2(b0, b1);
    }
    if (i < 8 * 8 * 32) {
        int lane = i & 31, t = (i >> 5) & 7, s = i >> 8;
        int t4 = lane & 3, g4 = lane >> 2;
        int k = 8 * s + t4, n = 8 * t + g4;
        g_fw2frag[i] = make_float2(tf32r(fw2[k * 64 + n]), tf32r(fw2[(k + 4) * 64 + n]));
    }
}

// ---------------------------------------------------------------------------
// node_pre: h = x @ l1w + l1b, and zero g_agg. 128 nodes/block, 2 barriers.
// ---------------------------------------------------------------------------
__global__ void __launch_bounds__(256)
node_pre_kernel(const float* __restrict__ x, const float* __restrict__ W,
                const float* __restrict__ b, int N) {
    __shared__ float xs[128 * 64];
    int tid = threadIdx.x;
    int j = tid & 63, q = tid >> 6;
    long n0 = (long)blockIdx.x * 128;
    uint32_t sb = (uint32_t)__cvta_generic_to_shared(xs);
    for (int i = tid; i < 2048; i += 256) {
        long node = n0 + (i >> 4);
        cp16(sb + i * 16, x + node * 64 + (i & 15) * 4, node < N ? 16 : 0);
    }
    cp_commit();
    float Wc[64];
#pragma unroll
    for (int k = 0; k < 64; ++k) Wc[k] = W[k * 64 + j];
    float bj = b[j];
    cp_wait0();
    __syncthreads();
#pragma unroll 4
    for (int nn = 0; nn < 32; ++nn) {
        int r = nn * 4 + q;
        long node = n0 + r;
        float acc = bj;
        const float* xr = xs + r * 64;
#pragma unroll
        for (int k = 0; k < 64; k += 4) {
            float4 xv = *(const float4*)(xr + k);
            acc += xv.x * Wc[k] + xv.y * Wc[k + 1] + xv.z * Wc[k + 2] + xv.w * Wc[k + 3];
        }
        if (node < N) {
            g_h[node * 64 + j] = acc;
            g_agg[node * 64 + j] = 0.f;
        }
    }
}

// ---------------------------------------------------------------------------
// node_post: out = ssp(agg @ l2w + l2b) @ l3w + l3b + x0. 128 nodes/block.
// ---------------------------------------------------------------------------
__global__ void __launch_bounds__(256)
node_post_kernel(const float* __restrict__ x0, const float* __restrict__ W2,
                 const float* __restrict__ b2, const float* __restrict__ W3,
                 const float* __restrict__ b3, float* __restrict__ out, int N) {
    extern __shared__ float smp[];
    float* xs = smp;            // 128*64
    float* ts = smp + 8192;     // 128*64
    int tid = threadIdx.x;
    int j = tid & 63, q = tid >> 6;
    long n0 = (long)blockIdx.x * 128;
    uint32_t sb = (uint32_t)__cvta_generic_to_shared(xs);
    for (int i = tid; i < 2048; i += 256) {
        long node = n0 + (i >> 4);
        cp16(sb + i * 16, g_agg + node * 64 + (i & 15) * 4, node < N ? 16 : 0);
    }
    cp_commit();
    float W2c[64], W3c[64];
#pragma unroll
    for (int k = 0; k < 64; ++k) { W2c[k] = W2[k * 64 + j]; W3c[k] = W3[k * 64 + j]; }
    float b2j = b2[j], b3j = b3[j];
    cp_wait0();
    __syncthreads();
#pragma unroll 4
    for (int nn = 0; nn < 32; ++nn) {
        int r = nn * 4 + q;
        float acc = b2j;
        const float* xr = xs + r * 64;
#pragma unroll
        for (int k = 0; k < 64; k += 4) {
            float4 xv = *(const float4*)(xr + k);
            acc += xv.x * W2c[k] + xv.y * W2c[k + 1] + xv.z * W2c[k + 2] + xv.w * W2c[k + 3];
        }
        ts[r * 64 + j] = sspf(acc);
    }
    __syncthreads();
#pragma unroll 4
    for (int nn = 0; nn < 32; ++nn) {
        int r = nn * 4 + q;
        long node = n0 + r;
        float acc = b3j;
        const float* tr = ts + r * 64;
#pragma unroll
        for (int k = 0; k < 64; k += 4) {
            float4 tv = *(const float4*)(tr + k);
            acc += tv.x * W3c[k] + tv.y * W3c[k + 1] + tv.z * W3c[k + 2] + tv.w * W3c[k + 3];
        }
        if (node < N) out[node * 64 + j] = acc + x0[node * 64 + j];
    }
}

// ---------------------------------------------------------------------------
// edge kernel: persistent, TMA + full/empty mbarrier pipeline (no per-chunk
// CTA barriers -> warps drift), resident fragment weights, shuffle handoff.
// ---------------------------------------------------------------------------
#define OFF_A   0        // 2 bufs x 256 rows x 32 cols = 16384 (64KB)
#define OFF_FW1 16384    // 10240 float2 = 20480 floats (80KB)
#define OFF_FW2 36864    // 2048 float2 = 4096 floats (16KB)
#define OFF_C   40960    // 256 x 64 = 16384 (64KB)
#define OFF_B1  57344
#define OFF_B2  57408
#define OFF_MB  57472    // 4 mbarriers: full0, full1, empty0, empty1
#define SMEM_FLOATS 57480
#define CSW(r, c) ((r) * 64 + ((c) ^ (((r) & 7) << 2)))

__global__ void __launch_bounds__(512, 1)
edge_kernel(const __grid_constant__ CUtensorMap tmap, const void* __restrict__ ei,
            const float* __restrict__ dist, const float* __restrict__ cutoff,
            const float* __restrict__ fb1, const float* __restrict__ fb2,
            int E, int NT, int GRIDSZ) {
    extern __shared__ __align__(1024) float sm[];
    uint32_t sbase = (uint32_t)__cvta_generic_to_shared(sm);
    int tid = threadIdx.x, lane = tid & 31, warp = tid >> 5;
    int t4 = lane & 3, g4 = lane >> 2, rw = warp * 16;
    const float2* FW1 = (const float2*)(sm + OFF_FW1);
    const float2* FW2 = (const float2*)(sm + OFF_FW2);
    uint32_t fullb[2]  = {sbase + OFF_MB * 4,      sbase + OFF_MB * 4 + 8};
    uint32_t emptyb[2] = {sbase + OFF_MB * 4 + 16, sbase + OFF_MB * 4 + 24};

    for (int i = tid; i < 5120; i += 512)
        cp16(sbase + (OFF_FW1 + i * 4) * 4, (const char*)g_fw1frag + i * 16, 16);
    for (int i = tid; i < 1024; i += 512)
        cp16(sbase + (OFF_FW2 + i * 4) * 4, (const char*)g_fw2frag + i * 16, 16);
    cp_commit();
    if (tid < 64) { sm[OFF_B1 + tid] = fb1[tid]; sm[OFF_B2 + tid] = fb2[tid]; }
    if (tid == 0) {
        mbar_init(fullb[0], 1);  mbar_init(fullb[1], 1);
        mbar_init(emptyb[0], 16); mbar_init(emptyb[1], 16);
    }
    cp_wait0();
    asm volatile("fence.proxy.async.shared::cta;" ::: "memory");
    __syncthreads();

    int is64 = g_is64;
    float picf = 3.14159265f / (*cutoff);

    auto issue = [&](long t, int c, int b) {
        if (t >= (long)NT) return;
        mbar_expect(fullb[b], 32768u);
        tma2d(sbase + (OFF_A + b * 8192) * 4, (const void*)&tmap,
              c * 32, (int)(t * TILE), fullb[b]);
    };

    long tile = blockIdx.x;
    if (tid == 0) { issue(tile, 0, 0); issue(tile, 1, 1); }
    int fp0 = 0, fp1 = 0, ep0 = 0, ep1 = 0;

    int el = tid >> 1, half = tid & 1;
    int u = t4 >> 1, p = t4 & 1;
    int l1 = 4 * g4 + u, l2 = l1 + 2;

    for (; tile < (long)NT; tile += GRIDSZ) {
        long e0 = tile * TILE;

        // preload epilogue indices/dist early (hide L2 latency behind GEMM1)
        long e = e0 + el;
        long long dstn = 0, srcn = 0;
        float f = 0.f;
        if (e < (long)E) {
            if (is64) {
                const long long* pp = (const long long*)ei;
                dstn = pp[e]; srcn = pp[(long)E + e];
            } else {
                const int* pp = (const int*)ei;
                dstn = pp[e]; srcn = pp[(long)E + e];
            }
            dstn = dstn < 0 ? 0 : (dstn >= NMAX ? NMAX - 1 : dstn);
            srcn = srcn < 0 ? 0 : (srcn >= NMAX ? NMAX - 1 : srcn);
            f = 1.f + __cosf(picf * dist[e]);
        }

        float acc[8][4];
#pragma unroll
        for (int t = 0; t < 8; ++t)
#pragma unroll
            for (int jj = 0; jj < 4; ++jj) acc[t][jj] = 0.f;

#pragma unroll 1
        for (int c = 0; c < 10; ++c) {
            int b = c & 1;
            if (b) { mbar_wait(fullb[1], fp1); fp1 ^= 1; }
            else   { mbar_wait(fullb[0], fp0); fp0 ^= 1; }
            const float* A = sm + OFF_A + b * 8192;
            int r0 = rw + g4, r1 = r0 + 8;
            int sw = g4 << 2;
#pragma unroll
            for (int s = 0; s < 4; ++s) {
                int w0 = 8 * s + t4;
                uint32_t a0 = cvt_tf32(A[r0 * 32 + (w0 ^ sw)]);
                uint32_t a1 = cvt_tf32(A[r1 * 32 + (w0 ^ sw)]);
                uint32_t a2 = cvt_tf32(A[r0 * 32 + ((w0 + 4) ^ sw)]);
                uint32_t a3 = cvt_tf32(A[r1 * 32 + ((w0 + 4) ^ sw)]);
#pragma unroll
                for (int t = 0; t < 8; ++t) {
                    float2 bb = FW1[((c * 4 + s) * 8 + t) * 32 + lane];
                    mma_tf32(acc[t], a0, a1, a2, a3,
                             __float_as_uint(bb.x), __float_as_uint(bb.y));
                }
            }
            // consumer done with buffer b for this chunk
            __syncwarp();
            if (lane == 0) mbar_arrive(b ? emptyb[1] : emptyb[0]);
            // producer: wait for drain, then refill with next chunk
            if (tid == 0) {
                if (b) { mbar_wait(emptyb[1], ep1); ep1 ^= 1; }
                else   { mbar_wait(emptyb[0], ep0); ep0 ^= 1; }
                if (c < 8) issue(tile, c + 2, b);
                else issue(tile + GRIDSZ, c - 8, b);
            }
        }

        // bias + ssp in-place on acc
#pragma unroll
        for (int t = 0; t < 8; ++t) {
            int cb = 8 * t + 2 * t4;
            float b0v = sm[OFF_B1 + cb], b1v = sm[OFF_B1 + cb + 1];
            acc[t][0] = sspf(acc[t][0] + b0v);
            acc[t][1] = sspf(acc[t][1] + b1v);
            acc[t][2] = sspf(acc[t][2] + b0v);
            acc[t][3] = sspf(acc[t][3] + b1v);
        }

        // GEMM2 with A-fragments gathered via warp shuffles
        float acc2[8][4];
#pragma unroll
        for (int t = 0; t < 8; ++t)
#pragma unroll
            for (int jj = 0; jj < 4; ++jj) acc2[t][jj] = 0.f;
#pragma unroll
        for (int s = 0; s < 8; ++s) {
            float v00 = __shfl_sync(0xffffffffu, acc[s][0], l1);
            float v01 = __shfl_sync(0xffffffffu, acc[s][1], l1);
            float v10 = __shfl_sync(0xffffffffu, acc[s][2], l1);
            float v11 = __shfl_sync(0xffffffffu, acc[s][3], l1);
            float w00 = __shfl_sync(0xffffffffu, acc[s][0], l2);
            float w01 = __shfl_sync(0xffffffffu, acc[s][1], l2);
            float w10 = __shfl_sync(0xffffffffu, acc[s][2], l2);
            float w11 = __shfl_sync(0xffffffffu, acc[s][3], l2);
            uint32_t a0 = cvt_tf32(p ? v01 : v00);
            uint32_t a1 = cvt_tf32(p ? v11 : v10);
            uint32_t a2 = cvt_tf32(p ? w01 : w00);
            uint32_t a3 = cvt_tf32(p ? w11 : w10);
#pragma unroll
            for (int t = 0; t < 8; ++t) {
                float2 bb = FW2[(s * 8 + t) * 32 + lane];
                mma_tf32(acc2[t], a0, a1, a2, a3,
                         __float_as_uint(bb.x), __float_as_uint(bb.y));
            }
        }

        // bias + ssp -> C (for per-edge epilogue access)
#pragma unroll
        for (int t = 0; t < 8; ++t) {
            int cb = 8 * t + 2 * t4;
            float b0v = sm[OFF_B2 + cb], b1v = sm[OFF_B2 + cb + 1];
            *(float2*)&sm[OFF_C + CSW(rw + g4, cb)] =
                make_float2(sspf(acc2[t][0] + b0v), sspf(acc2[t][1] + b1v));
            *(float2*)&sm[OFF_C + CSW(rw + g4 + 8, cb)] =
                make_float2(sspf(acc2[t][2] + b0v), sspf(acc2[t][3] + b1v));
        }
        __syncthreads();

        // epilogue: gather h[src], scatter atomics into agg[dst]
        if (e < (long)E) {
            const float* hrow = g_h + (long)srcn * 64 + half * 32;
            float* arow = g_agg + (long)dstn * 64 + half * 32;
#pragma unroll
            for (int jj = 0; jj < 8; ++jj) {
                float4 w = *(const float4*)&sm[OFF_C + CSW(el, half * 32 + 4 * jj)];
                float4 h4 = *(const float4*)(hrow + 4 * jj);
                atomicAdd((float4*)(arow + 4 * jj),
                          make_float4(w.x * h4.x * f, w.y * h4.y * f,
                                      w.z * h4.z * f, w.w * h4.w * f));
            }
        }
        __syncthreads();
    }
}

// ---------------------------------------------------------------------------
typedef CUresult (*PFN_tmencode)(
    CUtensorMap*, CUtensorMapDataType, cuuint32_t, void*,
    const cuuint64_t*, const cuuint64_t*, const cuuint32_t*, const cuuint32_t*,
    CUtensorMapInterleave, CUtensorMapSwizzle, CUtensorMapL2promotion,
    CUtensorMapFloatOOBfill);

extern "C" void kernel_launch(void* const* d_in, const int* in_sizes, int n_in,
                              void* d_out, int out_size) {
    const void* ei       = d_in[0];
    const float* x       = (const float*)d_in[1];
    const float* rbf     = (const float*)d_in[2];
    const float* dist    = (const float*)d_in[3];
    const float* cutoff  = (const float*)d_in[4];
    const float* fw1     = (const float*)d_in[5];
    const float* fb1     = (const float*)d_in[6];
    const float* fw2     = (const float*)d_in[7];
    const float* fb2     = (const float*)d_in[8];
    const float* l1w     = (const float*)d_in[9];
    const float* l1b     = (const float*)d_in[10];
    const float* l2w     = (const float*)d_in[11];
    const float* l2b     = (const float*)d_in[12];
    const float* l3w     = (const float*)d_in[13];
    const float* l3b     = (const float*)d_in[14];

    int E = in_sizes[0] / 2;
    int N = in_sizes[1] / 64;
    int NT = (E + TILE - 1) / TILE;
    int NB = (N + 127) / 128;

    static PFN_tmencode enc = nullptr;
    if (!enc) {
        cudaDriverEntryPointQueryResult st;
        cudaGetDriverEntryPointByVersion("cuTensorMapEncodeTiled", (void**)&enc,
                                         12000, cudaEnableDefault, &st);
    }
    alignas(64) CUtensorMap tmap;
    {
        cuuint64_t dims[2]    = {(cuuint64_t)RK, (cuuint64_t)E};
        cuuint64_t strides[1] = {(cuuint64_t)RK * 4};
        cuuint32_t box[2]     = {32, TILE};
        cuuint32_t estr[2]    = {1, 1};
        enc(&tmap, CU_TENSOR_MAP_DATA_TYPE_FLOAT32, 2, (void*)rbf,
            dims, strides, box, estr,
            CU_TENSOR_MAP_INTERLEAVE_NONE, CU_TENSOR_MAP_SWIZZLE_128B,
            CU_TENSOR_MAP_L2_PROMOTION_L2_128B, CU_TENSOR_MAP_FLOAT_OOB_FILL_NONE);
    }

    static int sms = 0;
    if (!sms) cudaDeviceGetAttribute(&sms, cudaDevAttrMultiProcessorCount, 0);
    int grid = sms > 0 ? sms : 148;

    cudaFuncSetAttribute(edge_kernel, cudaFuncAttributeMaxDynamicSharedMemorySize,
                         SMEM_FLOATS * 4);
    cudaFuncSetAttribute(node_post_kernel, cudaFuncAttributeMaxDynamicSharedMemorySize,
                         65536);

    detect_idx_kernel<<<1, 32>>>((const int*)ei);
    prep_frag_kernel<<<(10 * 4 * 8 * 32 + 255) / 256, 256>>>(fw1, fw2);
    node_pre_kernel<<<NB, 256>>>(x, l1w, l1b, N);
    edge_kernel<<<grid, 512, SMEM_FLOATS * 4>>>(tmap, ei, dist, cutoff,
                                                fb1, fb2, E, NT, grid);
    node_post_kernel<<<NB, 256, 65536>>>(x, l2w, l2b, l3w, l3b, (float*)d_out, N);
}

// round 10
// speedup vs baseline: 1.0096x; 1.0090x over previous
#include <cuda_runtime.h>
#include <cuda.h>
#include <cstdint>

#define NMAX 50000
#define RK 300
#define TILE 256

__device__ float g_h[NMAX * 64];
__device__ float g_agg[NMAX * 64];
__device__ float4 g_fw1q[10 * 4 * 4 * 32];  // [c][s][tp][lane] -> (b0_t,b1_t,b0_t1,b1_t1)
__device__ float4 g_fw2q[8 * 4 * 32];       // [s][tp][lane]
__device__ int g_is64;

__device__ __forceinline__ float sspf(float x) {
    float t = __expf(-fabsf(x));
    return fmaxf(x, 0.f) + __logf(1.f + t) - 0.69314718055994531f;
}
__device__ __forceinline__ uint32_t cvt_tf32(float x) {
    uint32_t r; asm("cvt.rna.tf32.f32 %0, %1;" : "=r"(r) : "f"(x)); return r;
}
__device__ __forceinline__ float tf32r(float x) { return __uint_as_float(cvt_tf32(x)); }

__device__ __forceinline__ void mma_tf32(float d[4], uint32_t a0, uint32_t a1,
                                         uint32_t a2, uint32_t a3,
                                         uint32_t b0, uint32_t b1) {
    asm volatile(
        "mma.sync.aligned.m16n8k8.row.col.f32.tf32.tf32.f32 "
        "{%0,%1,%2,%3}, {%4,%5,%6,%7}, {%8,%9}, {%0,%1,%2,%3};"
        : "+f"(d[0]), "+f"(d[1]), "+f"(d[2]), "+f"(d[3])
        : "r"(a0), "r"(a1), "r"(a2), "r"(a3), "r"(b0), "r"(b1));
}
__device__ __forceinline__ void cp16(uint32_t saddr, const void* g, int sz) {
    asm volatile("cp.async.cg.shared.global [%0], [%1], 16, %2;"
                 :: "r"(saddr), "l"(g), "r"(sz));
}
__device__ __forceinline__ void cp_commit() { asm volatile("cp.async.commit_group;"); }
__device__ __forceinline__ void cp_wait0()  { asm volatile("cp.async.wait_group 0;"); }

__device__ __forceinline__ void tma2d(uint32_t dst, const void* map, int x, int y,
                                      uint32_t mbar) {
    asm volatile(
        "cp.async.bulk.tensor.2d.shared::cta.global.tile.mbarrier::complete_tx::bytes "
        "[%0], [%1, {%2, %3}], [%4];"
        :: "r"(dst), "l"(map), "r"(x), "r"(y), "r"(mbar) : "memory");
}
__device__ __forceinline__ void mbar_init(uint32_t a, uint32_t cnt) {
    asm volatile("mbarrier.init.shared.b64 [%0], %1;" :: "r"(a), "r"(cnt) : "memory");
}
__device__ __forceinline__ void mbar_expect(uint32_t a, uint32_t tx) {
    asm volatile("mbarrier.arrive.expect_tx.shared.b64 _, [%0], %1;"
                 :: "r"(a), "r"(tx) : "memory");
}
__device__ __forceinline__ void mbar_wait(uint32_t a, uint32_t ph) {
    uint32_t done = 0;
    do {
        asm volatile(
            "{\n\t.reg .pred p;\n\t"
            "mbarrier.try_wait.parity.acquire.cta.shared::cta.b64 p, [%1], %2, 0x989680;\n\t"
            "selp.b32 %0, 1, 0, p;\n\t}"
            : "=r"(done) : "r"(a), "r"(ph) : "memory");
    } while (!done);
}

__global__ void detect_idx_kernel(const int* __restrict__ ei32) {
    if (threadIdx.x == 0 && blockIdx.x == 0) {
        int ornz = 0;
#pragma unroll
        for (int i = 0; i < 64; ++i) ornz |= ei32[2 * i + 1];
        g_is64 = (ornz == 0) ? 1 : 0;
    }
}

// fragment-major tf32 weights, float4-paired over adjacent t tiles.
// k = c*32 + 8s + t4 (+4 for second element), n = 16*tp + g4 (and +8)
__global__ void prep_frag_kernel(const float* __restrict__ fw1,
                                 const float* __restrict__ fw2) {
    int i = blockIdx.x * blockDim.x + threadIdx.x;
    if (i < 10 * 4 * 4 * 32) {
        int lane = i & 31, tp = (i >> 5) & 3, s = (i >> 7) & 3, c = i >> 9;
        int t4 = lane & 3, g4 = lane >> 2;
        int k = c * 32 + 8 * s + t4;
        int n0 = 16 * tp + g4, n1 = n0 + 8;
        float4 q;
        q.x = (k < RK) ? tf32r(fw1[k * 64 + n0]) : 0.f;
        q.y = (k + 4 < RK) ? tf32r(fw1[(k + 4) * 64 + n0]) : 0.f;
        q.z = (k < RK) ? tf32r(fw1[k * 64 + n1]) : 0.f;
        q.w = (k + 4 < RK) ? tf32r(fw1[(k + 4) * 64 + n1]) : 0.f;
        g_fw1q[i] = q;
    }
    if (i < 8 * 4 * 32) {
        int lane = i & 31, tp = (i >> 5) & 3, s = i >> 7;
        int t4 = lane & 3, g4 = lane >> 2;
        int k = 8 * s + t4;
        int n0 = 16 * tp + g4, n1 = n0 + 8;
        float4 q;
        q.x = tf32r(fw2[k * 64 + n0]);
        q.y = tf32r(fw2[(k + 4) * 64 + n0]);
        q.z = tf32r(fw2[k * 64 + n1]);
        q.w = tf32r(fw2[(k + 4) * 64 + n1]);
        g_fw2q[i] = q;
    }
}

// ---------------------------------------------------------------------------
// node kernels (proven R6 versions)
// ---------------------------------------------------------------------------
__global__ void __launch_bounds__(256)
node_pre_kernel(const float* __restrict__ x, const float* __restrict__ W,
                const float* __restrict__ b, int N) {
    __shared__ float xs[128 * 64];
    int tid = threadIdx.x;
    int j = tid & 63, q = tid >> 6;
    long n0 = (long)blockIdx.x * 128;
    uint32_t sb = (uint32_t)__cvta_generic_to_shared(xs);
    for (int i = tid; i < 2048; i += 256) {
        long node = n0 + (i >> 4);
        cp16(sb + i * 16, x + node * 64 + (i & 15) * 4, node < N ? 16 : 0);
    }
    cp_commit();
    float Wc[64];
#pragma unroll
    for (int k = 0; k < 64; ++k) Wc[k] = W[k * 64 + j];
    float bj = b[j];
    cp_wait0();
    __syncthreads();
#pragma unroll 4
    for (int nn = 0; nn < 32; ++nn) {
        int r = nn * 4 + q;
        long node = n0 + r;
        float acc = bj;
        const float* xr = xs + r * 64;
#pragma unroll
        for (int k = 0; k < 64; k += 4) {
            float4 xv = *(const float4*)(xr + k);
            acc += xv.x * Wc[k] + xv.y * Wc[k + 1] + xv.z * Wc[k + 2] + xv.w * Wc[k + 3];
        }
        if (node < N) {
            g_h[node * 64 + j] = acc;
            g_agg[node * 64 + j] = 0.f;
        }
    }
}

__global__ void __launch_bounds__(256)
node_post_kernel(const float* __restrict__ x0, const float* __restrict__ W2,
                 const float* __restrict__ b2, const float* __restrict__ W3,
                 const float* __restrict__ b3, float* __restrict__ out, int N) {
    extern __shared__ float smp[];
    float* xs = smp;
    float* ts = smp + 8192;
    int tid = threadIdx.x;
    int j = tid & 63, q = tid >> 6;
    long n0 = (long)blockIdx.x * 128;
    uint32_t sb = (uint32_t)__cvta_generic_to_shared(xs);
    for (int i = tid; i < 2048; i += 256) {
        long node = n0 + (i >> 4);
        cp16(sb + i * 16, g_agg + node * 64 + (i & 15) * 4, node < N ? 16 : 0);
    }
    cp_commit();
    float W2c[64], W3c[64];
#pragma unroll
    for (int k = 0; k < 64; ++k) { W2c[k] = W2[k * 64 + j]; W3c[k] = W3[k * 64 + j]; }
    float b2j = b2[j], b3j = b3[j];
    cp_wait0();
    __syncthreads();
#pragma unroll 4
    for (int nn = 0; nn < 32; ++nn) {
        int r = nn * 4 + q;
        float acc = b2j;
        const float* xr = xs + r * 64;
#pragma unroll
        for (int k = 0; k < 64; k += 4) {
            float4 xv = *(const float4*)(xr + k);
            acc += xv.x * W2c[k] + xv.y * W2c[k + 1] + xv.z * W2c[k + 2] + xv.w * W2c[k + 3];
        }
        ts[r * 64 + j] = sspf(acc);
    }
    __syncthreads();
#pragma unroll 4
    for (int nn = 0; nn < 32; ++nn) {
        int r = nn * 4 + q;
        long node = n0 + r;
        float acc = b3j;
        const float* tr = ts + r * 64;
#pragma unroll
        for (int k = 0; k < 64; k += 4) {
            float4 tv = *(const float4*)(tr + k);
            acc += tv.x * W3c[k] + tv.y * W3c[k + 1] + tv.z * W3c[k + 2] + tv.w * W3c[k + 3];
        }
        if (node < N) out[node * 64 + j] = acc + x0[node * 64 + j];
    }
}

// ---------------------------------------------------------------------------
// edge kernel: R6 structure (best), float4 B-frags, no runtime A cvt.
// ---------------------------------------------------------------------------
#define OFF_A   0        // 2 bufs x 256 rows x 32 cols = 16384 (64KB)
#define OFF_FW1 16384    // 5120 float4 = 20480 floats (80KB)
#define OFF_FW2 36864    // 1024 float4 = 4096 floats (16KB)
#define OFF_C   40960    // 256 x 64 = 16384 (64KB)
#define OFF_B1  57344
#define OFF_B2  57408
#define OFF_MB  57472    // 2 mbarriers
#define SMEM_FLOATS 57476
#define CSW(r, c) ((r) * 64 + ((c) ^ (((r) & 7) << 2)))
#define FU(x) __float_as_uint(x)

__global__ void __launch_bounds__(512, 1)
edge_kernel(const __grid_constant__ CUtensorMap tmap, const void* __restrict__ ei,
            const float* __restrict__ dist, const float* __restrict__ cutoff,
            const float* __restrict__ fb1, const float* __restrict__ fb2,
            int E, int NT, int GRIDSZ) {
    extern __shared__ __align__(1024) float sm[];
    uint32_t sbase = (uint32_t)__cvta_generic_to_shared(sm);
    int tid = threadIdx.x, lane = tid & 31, warp = tid >> 5;
    int t4 = lane & 3, g4 = lane >> 2, rw = warp * 16;
    const float4* FW1 = (const float4*)(sm + OFF_FW1);
    const float4* FW2 = (const float4*)(sm + OFF_FW2);
    uint32_t mb0 = sbase + OFF_MB * 4, mb1 = mb0 + 8;

    for (int i = tid; i < 5120; i += 512)
        cp16(sbase + (OFF_FW1 + i * 4) * 4, (const char*)g_fw1q + i * 16, 16);
    for (int i = tid; i < 1024; i += 512)
        cp16(sbase + (OFF_FW2 + i * 4) * 4, (const char*)g_fw2q + i * 16, 16);
    cp_commit();
    if (tid < 64) { sm[OFF_B1 + tid] = fb1[tid]; sm[OFF_B2 + tid] = fb2[tid]; }
    if (tid == 0) { mbar_init(mb0, 1); mbar_init(mb1, 1); }
    cp_wait0();
    asm volatile("fence.proxy.async.shared::cta;" ::: "memory");
    __syncthreads();

    int is64 = g_is64;
    float picf = 3.14159265f / (*cutoff);

    auto issue = [&](long t, int c, int b) {
        if (tid != 0 || t >= (long)NT) return;
        uint32_t mb = b ? mb1 : mb0;
        mbar_expect(mb, 32768u);
        tma2d(sbase + (OFF_A + b * 8192) * 4, (const void*)&tmap,
              c * 32, (int)(t * TILE), mb);
    };

    long tile = blockIdx.x;
    issue(tile, 0, 0);
    issue(tile, 1, 1);
    int ph0 = 0, ph1 = 0;

    int el = tid >> 1, half = tid & 1;
    int u = t4 >> 1, p = t4 & 1;
    int l1 = 4 * g4 + u, l2 = l1 + 2;

    for (; tile < (long)NT; tile += GRIDSZ) {
        long e0 = tile * TILE;

        // preload epilogue indices/dist early (hide L2 latency behind GEMM1)
        long e = e0 + el;
        long long dstn = 0, srcn = 0;
        float f = 0.f;
        if (e < (long)E) {
            if (is64) {
                const long long* pp = (const long long*)ei;
                dstn = pp[e]; srcn = pp[(long)E + e];
            } else {
                const int* pp = (const int*)ei;
                dstn = pp[e]; srcn = pp[(long)E + e];
            }
            dstn = dstn < 0 ? 0 : (dstn >= NMAX ? NMAX - 1 : dstn);
            srcn = srcn < 0 ? 0 : (srcn >= NMAX ? NMAX - 1 : srcn);
            f = 1.f + __cosf(picf * dist[e]);
        }

        float acc[8][4];
#pragma unroll
        for (int t = 0; t < 8; ++t)
#pragma unroll
            for (int jj = 0; jj < 4; ++jj) acc[t][jj] = 0.f;

#pragma unroll 1
        for (int c = 0; c < 10; ++c) {
            int b = c & 1;
            if (b) { mbar_wait(mb1, ph1); ph1 ^= 1; }
            else   { mbar_wait(mb0, ph0); ph0 ^= 1; }
            const float* A = sm + OFF_A + b * 8192;
            int r0 = rw + g4, r1 = r0 + 8;
            int sw = g4 << 2;
#pragma unroll
            for (int s = 0; s < 4; ++s) {
                int w0 = 8 * s + t4;
                uint32_t a0 = FU(A[r0 * 32 + (w0 ^ sw)]);
                uint32_t a1 = FU(A[r1 * 32 + (w0 ^ sw)]);
                uint32_t a2 = FU(A[r0 * 32 + ((w0 + 4) ^ sw)]);
                uint32_t a3 = FU(A[r1 * 32 + ((w0 + 4) ^ sw)]);
#pragma unroll
                for (int tp = 0; tp < 4; ++tp) {
                    float4 q = FW1[((c * 4 + s) * 4 + tp) * 32 + lane];
                    mma_tf32(acc[2 * tp], a0, a1, a2, a3, FU(q.x), FU(q.y));
                    mma_tf32(acc[2 * tp + 1], a0, a1, a2, a3, FU(q.z), FU(q.w));
                }
            }
            __syncthreads();
            if (c < 8) issue(tile, c + 2, b);
            else issue(tile + GRIDSZ, c - 8, b);
        }

        // bias + ssp in-place on acc
#pragma unroll
        for (int t = 0; t < 8; ++t) {
            int cb = 8 * t + 2 * t4;
            float b0v = sm[OFF_B1 + cb], b1v = sm[OFF_B1 + cb + 1];
            acc[t][0] = sspf(acc[t][0] + b0v);
            acc[t][1] = sspf(acc[t][1] + b1v);
            acc[t][2] = sspf(acc[t][2] + b0v);
            acc[t][3] = sspf(acc[t][3] + b1v);
        }

        // GEMM2 with A-fragments gathered via warp shuffles (no cvt; HW truncates)
        float acc2[8][4];
#pragma unroll
        for (int t = 0; t < 8; ++t)
#pragma unroll
            for (int jj = 0; jj < 4; ++jj) acc2[t][jj] = 0.f;
#pragma unroll
        for (int s = 0; s < 8; ++s) {
            float v00 = __shfl_sync(0xffffffffu, acc[s][0], l1);
            float v01 = __shfl_sync(0xffffffffu, acc[s][1], l1);
            float v10 = __shfl_sync(0xffffffffu, acc[s][2], l1);
            float v11 = __shfl_sync(0xffffffffu, acc[s][3], l1);
            float w00 = __shfl_sync(0xffffffffu, acc[s][0], l2);
            float w01 = __shfl_sync(0xffffffffu, acc[s][1], l2);
            float w10 = __shfl_sync(0xffffffffu, acc[s][2], l2);
            float w11 = __shfl_sync(0xffffffffu, acc[s][3], l2);
            uint32_t a0 = FU(p ? v01 : v00);
            uint32_t a1 = FU(p ? v11 : v10);
            uint32_t a2 = FU(p ? w01 : w00);
            uint32_t a3 = FU(p ? w11 : w10);
#pragma unroll
            for (int tp = 0; tp < 4; ++tp) {
                float4 q = FW2[(s * 4 + tp) * 32 + lane];
                mma_tf32(acc2[2 * tp], a0, a1, a2, a3, FU(q.x), FU(q.y));
                mma_tf32(acc2[2 * tp + 1], a0, a1, a2, a3, FU(q.z), FU(q.w));
            }
        }

        // bias + ssp -> C (for per-edge epilogue access)
#pragma unroll
        for (int t = 0; t < 8; ++t) {
            int cb = 8 * t + 2 * t4;
            float b0v = sm[OFF_B2 + cb], b1v = sm[OFF_B2 + cb + 1];
            *(float2*)&sm[OFF_C + CSW(rw + g4, cb)] =
                make_float2(sspf(acc2[t][0] + b0v), sspf(acc2[t][1] + b1v));
            *(float2*)&sm[OFF_C + CSW(rw + g4 + 8, cb)] =
                make_float2(sspf(acc2[t][2] + b0v), sspf(acc2[t][3] + b1v));
        }
        __syncthreads();

        // epilogue: gather h[src], scatter atomics into agg[dst]
        if (e < (long)E) {
            const float* hrow = g_h + (long)srcn * 64 + half * 32;
            float* arow = g_agg + (long)dstn * 64 + half * 32;
#pragma unroll
            for (int jj = 0; jj < 8; ++jj) {
                float4 w = *(const float4*)&sm[OFF_C + CSW(el, half * 32 + 4 * jj)];
                float4 h4 = *(const float4*)(hrow + 4 * jj);
                atomicAdd((float4*)(arow + 4 * jj),
                          make_float4(w.x * h4.x * f, w.y * h4.y * f,
                                      w.z * h4.z * f, w.w * h4.w * f));
            }
        }
        __syncthreads();
    }
}

// ---------------------------------------------------------------------------
typedef CUresult (*PFN_tmencode)(
    CUtensorMap*, CUtensorMapDataType, cuuint32_t, void*,
    const cuuint64_t*, const cuuint64_t*, const cuuint32_t*, const cuuint32_t*,
    CUtensorMapInterleave, CUtensorMapSwizzle, CUtensorMapL2promotion,
    CUtensorMapFloatOOBfill);

extern "C" void kernel_launch(void* const* d_in, const int* in_sizes, int n_in,
                              void* d_out, int out_size) {
    const void* ei       = d_in[0];
    const float* x       = (const float*)d_in[1];
    const float* rbf     = (const float*)d_in[2];
    const float* dist    = (const float*)d_in[3];
    const float* cutoff  = (const float*)d_in[4];
    const float* fw1     = (const float*)d_in[5];
    const float* fb1     = (const float*)d_in[6];
    const float* fw2     = (const float*)d_in[7];
    const float* fb2     = (const float*)d_in[8];
    const float* l1w     = (const float*)d_in[9];
    const float* l1b     = (const float*)d_in[10];
    const float* l2w     = (const float*)d_in[11];
    const float* l2b     = (const float*)d_in[12];
    const float* l3w     = (const float*)d_in[13];
    const float* l3b     = (const float*)d_in[14];

    int E = in_sizes[0] / 2;
    int N = in_sizes[1] / 64;
    int NT = (E + TILE - 1) / TILE;
    int NB = (N + 127) / 128;

    static PFN_tmencode enc = nullptr;
    if (!enc) {
        cudaDriverEntryPointQueryResult st;
        cudaGetDriverEntryPointByVersion("cuTensorMapEncodeTiled", (void**)&enc,
                                         12000, cudaEnableDefault, &st);
    }
    alignas(64) CUtensorMap tmap;
    {
        cuuint64_t dims[2]    = {(cuuint64_t)RK, (cuuint64_t)E};
        cuuint64_t strides[1] = {(cuuint64_t)RK * 4};
        cuuint32_t box[2]     = {32, TILE};
        cuuint32_t estr[2]    = {1, 1};
        enc(&tmap, CU_TENSOR_MAP_DATA_TYPE_FLOAT32, 2, (void*)rbf,
            dims, strides, box, estr,
            CU_TENSOR_MAP_INTERLEAVE_NONE, CU_TENSOR_MAP_SWIZZLE_128B,
            CU_TENSOR_MAP_L2_PROMOTION_L2_128B, CU_TENSOR_MAP_FLOAT_OOB_FILL_NONE);
    }

    static int sms = 0;
    if (!sms) cudaDeviceGetAttribute(&sms, cudaDevAttrMultiProcessorCount, 0);
    int grid = sms > 0 ? sms : 148;

    cudaFuncSetAttribute(edge_kernel, cudaFuncAttributeMaxDynamicSharedMemorySize,
                         SMEM_FLOATS * 4);
    cudaFuncSetAttribute(node_post_kernel, cudaFuncAttributeMaxDynamicSharedMemorySize,
                         65536);

    detect_idx_kernel<<<1, 32>>>((const int*)ei);
    prep_frag_kernel<<<(10 * 4 * 4 * 32 + 255) / 256, 256>>>(fw1, fw2);
    node_pre_kernel<<<NB, 256>>>(x, l1w, l1b, N);
    edge_kernel<<<grid, 512, SMEM_FLOATS * 4>>>(tmap, ei, dist, cutoff,
                                                fb1, fb2, E, NT, grid);
    node_post_kernel<<<NB, 256, 65536>>>(x, l2w, l2b, l3w, l3b, (float*)d_out, N);
}

// round 11
// speedup vs baseline: 1.0110x; 1.0013x over previous
#include <cuda_runtime.h>
#include <cuda.h>
#include <cstdint>

#define NMAX 50000
#define RK 300
#define TILE 128

__device__ float g_h[NMAX * 64];
__device__ float g_agg[NMAX * 64];
__device__ float4 g_fw1q[10 * 4 * 4 * 32];  // [c][s][tp][lane] -> (b0_t,b1_t,b0_t1,b1_t1)
__device__ float4 g_fw2q[8 * 4 * 32];       // [s][tp][lane]
__device__ int g_is64;

__device__ __forceinline__ float sspf(float x) {
    float t = __expf(-fabsf(x));
    return fmaxf(x, 0.f) + __logf(1.f + t) - 0.69314718055994531f;
}
__device__ __forceinline__ uint32_t cvt_tf32(float x) {
    uint32_t r; asm("cvt.rna.tf32.f32 %0, %1;" : "=r"(r) : "f"(x)); return r;
}
__device__ __forceinline__ float tf32r(float x) { return __uint_as_float(cvt_tf32(x)); }

__device__ __forceinline__ void mma_tf32(float d[4], uint32_t a0, uint32_t a1,
                                         uint32_t a2, uint32_t a3,
                                         uint32_t b0, uint32_t b1) {
    asm volatile(
        "mma.sync.aligned.m16n8k8.row.col.f32.tf32.tf32.f32 "
        "{%0,%1,%2,%3}, {%4,%5,%6,%7}, {%8,%9}, {%0,%1,%2,%3};"
        : "+f"(d[0]), "+f"(d[1]), "+f"(d[2]), "+f"(d[3])
        : "r"(a0), "r"(a1), "r"(a2), "r"(a3), "r"(b0), "r"(b1));
}
__device__ __forceinline__ void cp16(uint32_t saddr, const void* g, int sz) {
    asm volatile("cp.async.cg.shared.global [%0], [%1], 16, %2;"
                 :: "r"(saddr), "l"(g), "r"(sz));
}
__device__ __forceinline__ void cp_commit() { asm volatile("cp.async.commit_group;"); }
__device__ __forceinline__ void cp_wait0()  { asm volatile("cp.async.wait_group 0;"); }

__device__ __forceinline__ void tma2d(uint32_t dst, const void* map, int x, int y,
                                      uint32_t mbar) {
    asm volatile(
        "cp.async.bulk.tensor.2d.shared::cta.global.tile.mbarrier::complete_tx::bytes "
        "[%0], [%1, {%2, %3}], [%4];"
        :: "r"(dst), "l"(map), "r"(x), "r"(y), "r"(mbar) : "memory");
}
__device__ __forceinline__ void mbar_init(uint32_t a, uint32_t cnt) {
    asm volatile("mbarrier.init.shared.b64 [%0], %1;" :: "r"(a), "r"(cnt) : "memory");
}
__device__ __forceinline__ void mbar_expect(uint32_t a, uint32_t tx) {
    asm volatile("mbarrier.arrive.expect_tx.shared.b64 _, [%0], %1;"
                 :: "r"(a), "r"(tx) : "memory");
}
__device__ __forceinline__ void mbar_wait(uint32_t a, uint32_t ph) {
    uint32_t done = 0;
    do {
        asm volatile(
            "{\n\t.reg .pred p;\n\t"
            "mbarrier.try_wait.parity.acquire.cta.shared::cta.b64 p, [%1], %2, 0x989680;\n\t"
            "selp.b32 %0, 1, 0, p;\n\t}"
            : "=r"(done) : "r"(a), "r"(ph) : "memory");
    } while (!done);
}

__global__ void detect_idx_kernel(const int* __restrict__ ei32) {
    if (threadIdx.x == 0 && blockIdx.x == 0) {
        int ornz = 0;
#pragma unroll
        for (int i = 0; i < 64; ++i) ornz |= ei32[2 * i + 1];
        g_is64 = (ornz == 0) ? 1 : 0;
    }
}

// fragment-major tf32 weights, float4-paired over adjacent t tiles.
__global__ void prep_frag_kernel(const float* __restrict__ fw1,
                                 const float* __restrict__ fw2) {
    int i = blockIdx.x * blockDim.x + threadIdx.x;
    if (i < 10 * 4 * 4 * 32) {
        int lane = i & 31, tp = (i >> 5) & 3, s = (i >> 7) & 3, c = i >> 9;
        int t4 = lane & 3, g4 = lane >> 2;
        int k = c * 32 + 8 * s + t4;
        int n0 = 16 * tp + g4, n1 = n0 + 8;
        float4 q;
        q.x = (k < RK) ? tf32r(fw1[k * 64 + n0]) : 0.f;
        q.y = (k + 4 < RK) ? tf32r(fw1[(k + 4) * 64 + n0]) : 0.f;
        q.z = (k < RK) ? tf32r(fw1[k * 64 + n1]) : 0.f;
        q.w = (k + 4 < RK) ? tf32r(fw1[(k + 4) * 64 + n1]) : 0.f;
        g_fw1q[i] = q;
    }
    if (i < 8 * 4 * 32) {
        int lane = i & 31, tp = (i >> 5) & 3, s = i >> 7;
        int t4 = lane & 3, g4 = lane >> 2;
        int k = 8 * s + t4;
        int n0 = 16 * tp + g4, n1 = n0 + 8;
        float4 q;
        q.x = tf32r(fw2[k * 64 + n0]);
        q.y = tf32r(fw2[(k + 4) * 64 + n0]);
        q.z = tf32r(fw2[k * 64 + n1]);
        q.w = tf32r(fw2[(k + 4) * 64 + n1]);
        g_fw2q[i] = q;
    }
}

// ---------------------------------------------------------------------------
// node kernels (proven R6 versions)
// ---------------------------------------------------------------------------
__global__ void __launch_bounds__(256)
node_pre_kernel(const float* __restrict__ x, const float* __restrict__ W,
                const float* __restrict__ b, int N) {
    __shared__ float xs[128 * 64];
    int tid = threadIdx.x;
    int j = tid & 63, q = tid >> 6;
    long n0 = (long)blockIdx.x * 128;
    uint32_t sb = (uint32_t)__cvta_generic_to_shared(xs);
    for (int i = tid; i < 2048; i += 256) {
        long node = n0 + (i >> 4);
        cp16(sb + i * 16, x + node * 64 + (i & 15) * 4, node < N ? 16 : 0);
    }
    cp_commit();
    float Wc[64];
#pragma unroll
    for (int k = 0; k < 64; ++k) Wc[k] = W[k * 64 + j];
    float bj = b[j];
    cp_wait0();
    __syncthreads();
#pragma unroll 4
    for (int nn = 0; nn < 32; ++nn) {
        int r = nn * 4 + q;
        long node = n0 + r;
        float acc = bj;
        const float* xr = xs + r * 64;
#pragma unroll
        for (int k = 0; k < 64; k += 4) {
            float4 xv = *(const float4*)(xr + k);
            acc += xv.x * Wc[k] + xv.y * Wc[k + 1] + xv.z * Wc[k + 2] + xv.w * Wc[k + 3];
        }
        if (node < N) {
            g_h[node * 64 + j] = acc;
            g_agg[node * 64 + j] = 0.f;
        }
    }
}

__global__ void __launch_bounds__(256)
node_post_kernel(const float* __restrict__ x0, const float* __restrict__ W2,
                 const float* __restrict__ b2, const float* __restrict__ W3,
                 const float* __restrict__ b3, float* __restrict__ out, int N) {
    extern __shared__ float smp[];
    float* xs = smp;
    float* ts = smp + 8192;
    int tid = threadIdx.x;
    int j = tid & 63, q = tid >> 6;
    long n0 = (long)blockIdx.x * 128;
    uint32_t sb = (uint32_t)__cvta_generic_to_shared(xs);
    for (int i = tid; i < 2048; i += 256) {
        long node = n0 + (i >> 4);
        cp16(sb + i * 16, g_agg + node * 64 + (i & 15) * 4, node < N ? 16 : 0);
    }
    cp_commit();
    float W2c[64], W3c[64];
#pragma unroll
    for (int k = 0; k < 64; ++k) { W2c[k] = W2[k * 64 + j]; W3c[k] = W3[k * 64 + j]; }
    float b2j = b2[j], b3j = b3[j];
    cp_wait0();
    __syncthreads();
#pragma unroll 4
    for (int nn = 0; nn < 32; ++nn) {
        int r = nn * 4 + q;
        float acc = b2j;
        const float* xr = xs + r * 64;
#pragma unroll
        for (int k = 0; k < 64; k += 4) {
            float4 xv = *(const float4*)(xr + k);
            acc += xv.x * W2c[k] + xv.y * W2c[k + 1] + xv.z * W2c[k + 2] + xv.w * W2c[k + 3];
        }
        ts[r * 64 + j] = sspf(acc);
    }
    __syncthreads();
#pragma unroll 4
    for (int nn = 0; nn < 32; ++nn) {
        int r = nn * 4 + q;
        long node = n0 + r;
        float acc = b3j;
        const float* tr = ts + r * 64;
#pragma unroll
        for (int k = 0; k < 64; k += 4) {
            float4 tv = *(const float4*)(tr + k);
            acc += tv.x * W3c[k] + tv.y * W3c[k + 1] + tv.z * W3c[k + 2] + tv.w * W3c[k + 3];
        }
        if (node < N) out[node * 64 + j] = acc + x0[node * 64 + j];
    }
}

// ---------------------------------------------------------------------------
// edge kernel: 3 CTAs/SM, 256 thr, TILE=128, B-frags via __ldg (L2-resident),
// TMA A double-buffer, shuffle GEMM1->GEMM2 handoff. Non-persistent grid.
// smem floats:
#define OFF_A   0        // 2 bufs x 128 rows x 32 = 8192 (32KB)
#define OFF_C   8192     // 128 x 64 = 8192 (32KB)
#define OFF_B1  16384
#define OFF_B2  16448
#define OFF_MB  16512    // 2 mbarriers
#define SMEM_FLOATS 16516
#define CSW(r, c) ((r) * 64 + ((c) ^ (((r) & 7) << 2)))
#define FU(x) __float_as_uint(x)

__global__ void __launch_bounds__(256, 3)
edge_kernel(const __grid_constant__ CUtensorMap tmap, const void* __restrict__ ei,
            const float* __restrict__ dist, const float* __restrict__ cutoff,
            const float* __restrict__ fb1, const float* __restrict__ fb2,
            int E) {
    extern __shared__ __align__(1024) float sm[];
    uint32_t sbase = (uint32_t)__cvta_generic_to_shared(sm);
    int tid = threadIdx.x, lane = tid & 31, warp = tid >> 5;
    int t4 = lane & 3, g4 = lane >> 2, rw = warp * 16;
    uint32_t mb0 = sbase + OFF_MB * 4, mb1 = mb0 + 8;
    long e0 = (long)blockIdx.x * TILE;

    if (tid < 64) { sm[OFF_B1 + tid] = fb1[tid]; sm[OFF_B2 + tid] = fb2[tid]; }
    if (tid == 0) { mbar_init(mb0, 1); mbar_init(mb1, 1); }
    __syncthreads();
    if (tid == 0) {
        mbar_expect(mb0, 16384u);
        tma2d(sbase + OFF_A * 4, (const void*)&tmap, 0, (int)e0, mb0);
        mbar_expect(mb1, 16384u);
        tma2d(sbase + (OFF_A + 4096) * 4, (const void*)&tmap, 32, (int)e0, mb1);
    }

    int is64 = g_is64;
    float picf = 3.14159265f / (*cutoff);

    float acc[8][4];
#pragma unroll
    for (int t = 0; t < 8; ++t)
#pragma unroll
        for (int jj = 0; jj < 4; ++jj) acc[t][jj] = 0.f;

    const float4* B1p = g_fw1q + lane;
    int ph0 = 0, ph1 = 0;

#pragma unroll 1
    for (int c = 0; c < 10; ++c) {
        int b = c & 1;
        if (b) { mbar_wait(mb1, ph1); ph1 ^= 1; }
        else   { mbar_wait(mb0, ph0); ph0 ^= 1; }
        const float* A = sm + OFF_A + b * 4096;
        int r0 = rw + g4, r1 = r0 + 8;
        int sw = g4 << 2;
        const float4* Bc = B1p + c * 512;
        // prefetch s=0 B frags
        float4 qa0 = __ldg(Bc), qa1 = __ldg(Bc + 32), qa2 = __ldg(Bc + 64),
               qa3 = __ldg(Bc + 96);
#pragma unroll
        for (int s = 0; s < 4; ++s) {
            float4 qb0, qb1, qb2, qb3;
            if (s < 3) {
                const float4* Bn = Bc + (s + 1) * 128;
                qb0 = __ldg(Bn); qb1 = __ldg(Bn + 32);
                qb2 = __ldg(Bn + 64); qb3 = __ldg(Bn + 96);
            }
            int w0 = 8 * s + t4;
            uint32_t a0 = FU(A[r0 * 32 + (w0 ^ sw)]);
            uint32_t a1 = FU(A[r1 * 32 + (w0 ^ sw)]);
            uint32_t a2 = FU(A[r0 * 32 + ((w0 + 4) ^ sw)]);
            uint32_t a3 = FU(A[r1 * 32 + ((w0 + 4) ^ sw)]);
            mma_tf32(acc[0], a0, a1, a2, a3, FU(qa0.x), FU(qa0.y));
            mma_tf32(acc[1], a0, a1, a2, a3, FU(qa0.z), FU(qa0.w));
            mma_tf32(acc[2], a0, a1, a2, a3, FU(qa1.x), FU(qa1.y));
            mma_tf32(acc[3], a0, a1, a2, a3, FU(qa1.z), FU(qa1.w));
            mma_tf32(acc[4], a0, a1, a2, a3, FU(qa2.x), FU(qa2.y));
            mma_tf32(acc[5], a0, a1, a2, a3, FU(qa2.z), FU(qa2.w));
            mma_tf32(acc[6], a0, a1, a2, a3, FU(qa3.x), FU(qa3.y));
            mma_tf32(acc[7], a0, a1, a2, a3, FU(qa3.z), FU(qa3.w));
            qa0 = qb0; qa1 = qb1; qa2 = qb2; qa3 = qb3;
        }
        __syncthreads();
        if (tid == 0 && c < 8) {
            uint32_t mb = b ? mb1 : mb0;
            mbar_expect(mb, 16384u);
            tma2d(sbase + (OFF_A + b * 4096) * 4, (const void*)&tmap,
                  (c + 2) * 32, (int)e0, mb);
        }
    }

    // epilogue index/dist preload (overlaps GEMM2)
    int el = tid >> 1, half = tid & 1;
    long e = e0 + el;
    long long dstn = 0, srcn = 0;
    float f = 0.f;
    if (e < (long)E) {
        if (is64) {
            const long long* pp = (const long long*)ei;
            dstn = pp[e]; srcn = pp[(long)E + e];
        } else {
            const int* pp = (const int*)ei;
            dstn = pp[e]; srcn = pp[(long)E + e];
        }
        dstn = dstn < 0 ? 0 : (dstn >= NMAX ? NMAX - 1 : dstn);
        srcn = srcn < 0 ? 0 : (srcn >= NMAX ? NMAX - 1 : srcn);
        f = 1.f + __cosf(picf * dist[e]);
    }

    // bias + ssp in-place on acc
#pragma unroll
    for (int t = 0; t < 8; ++t) {
        int cb = 8 * t + 2 * t4;
        float b0v = sm[OFF_B1 + cb], b1v = sm[OFF_B1 + cb + 1];
        acc[t][0] = sspf(acc[t][0] + b0v);
        acc[t][1] = sspf(acc[t][1] + b1v);
        acc[t][2] = sspf(acc[t][2] + b0v);
        acc[t][3] = sspf(acc[t][3] + b1v);
    }

    // GEMM2 via shuffle handoff
    int u = t4 >> 1, p = t4 & 1;
    int l1 = 4 * g4 + u, l2 = l1 + 2;
    float acc2[8][4];
#pragma unroll
    for (int t = 0; t < 8; ++t)
#pragma unroll
        for (int jj = 0; jj < 4; ++jj) acc2[t][jj] = 0.f;
#pragma unroll
    for (int s = 0; s < 8; ++s) {
        float v00 = __shfl_sync(0xffffffffu, acc[s][0], l1);
        float v01 = __shfl_sync(0xffffffffu, acc[s][1], l1);
        float v10 = __shfl_sync(0xffffffffu, acc[s][2], l1);
        float v11 = __shfl_sync(0xffffffffu, acc[s][3], l1);
        float w00 = __shfl_sync(0xffffffffu, acc[s][0], l2);
        float w01 = __shfl_sync(0xffffffffu, acc[s][1], l2);
        float w10 = __shfl_sync(0xffffffffu, acc[s][2], l2);
        float w11 = __shfl_sync(0xffffffffu, acc[s][3], l2);
        uint32_t a0 = FU(p ? v01 : v00);
        uint32_t a1 = FU(p ? v11 : v10);
        uint32_t a2 = FU(p ? w01 : w00);
        uint32_t a3 = FU(p ? w11 : w10);
        const float4* B2p = g_fw2q + s * 128 + lane;
#pragma unroll
        for (int tp = 0; tp < 4; ++tp) {
            float4 q = __ldg(B2p + tp * 32);
            mma_tf32(acc2[2 * tp], a0, a1, a2, a3, FU(q.x), FU(q.y));
            mma_tf32(acc2[2 * tp + 1], a0, a1, a2, a3, FU(q.z), FU(q.w));
        }
    }

    // bias + ssp -> C (swizzled) for per-edge epilogue
#pragma unroll
    for (int t = 0; t < 8; ++t) {
        int cb = 8 * t + 2 * t4;
        float b0v = sm[OFF_B2 + cb], b1v = sm[OFF_B2 + cb + 1];
        *(float2*)&sm[OFF_C + CSW(rw + g4, cb)] =
            make_float2(sspf(acc2[t][0] + b0v), sspf(acc2[t][1] + b1v));
        *(float2*)&sm[OFF_C + CSW(rw + g4 + 8, cb)] =
            make_float2(sspf(acc2[t][2] + b0v), sspf(acc2[t][3] + b1v));
    }
    __syncthreads();

    // epilogue: gather h[src], scatter atomics into agg[dst]
    if (e < (long)E) {
        const float* hrow = g_h + (long)srcn * 64 + half * 32;
        float* arow = g_agg + (long)dstn * 64 + half * 32;
#pragma unroll
        for (int jj = 0; jj < 8; ++jj) {
            float4 w = *(const float4*)&sm[OFF_C + CSW(el, half * 32 + 4 * jj)];
            float4 h4 = *(const float4*)(hrow + 4 * jj);
            atomicAdd((float4*)(arow + 4 * jj),
                      make_float4(w.x * h4.x * f, w.y * h4.y * f,
                                  w.z * h4.z * f, w.w * h4.w * f));
        }
    }
}

// ---------------------------------------------------------------------------
typedef CUresult (*PFN_tmencode)(
    CUtensorMap*, CUtensorMapDataType, cuuint32_t, void*,
    const cuuint64_t*, const cuuint64_t*, const cuuint32_t*, const cuuint32_t*,
    CUtensorMapInterleave, CUtensorMapSwizzle, CUtensorMapL2promotion,
    CUtensorMapFloatOOBfill);

extern "C" void kernel_launch(void* const* d_in, const int* in_sizes, int n_in,
                              void* d_out, int out_size) {
    const void* ei       = d_in[0];
    const float* x       = (const float*)d_in[1];
    const float* rbf     = (const float*)d_in[2];
    const float* dist    = (const float*)d_in[3];
    const float* cutoff  = (const float*)d_in[4];
    const float* fw1     = (const float*)d_in[5];
    const float* fb1     = (const float*)d_in[6];
    const float* fw2     = (const float*)d_in[7];
    const float* fb2     = (const float*)d_in[8];
    const float* l1w     = (const float*)d_in[9];
    const float* l1b     = (const float*)d_in[10];
    const float* l2w     = (const float*)d_in[11];
    const float* l2b     = (const float*)d_in[12];
    const float* l3w     = (const float*)d_in[13];
    const float* l3b     = (const float*)d_in[14];

    int E = in_sizes[0] / 2;
    int N = in_sizes[1] / 64;
    int NT = (E + TILE - 1) / TILE;
    int NB = (N + 127) / 128;

    static PFN_tmencode enc = nullptr;
    if (!enc) {
        cudaDriverEntryPointQueryResult st;
        cudaGetDriverEntryPointByVersion("cuTensorMapEncodeTiled", (void**)&enc,
                                         12000, cudaEnableDefault, &st);
    }
    alignas(64) CUtensorMap tmap;
    {
        cuuint64_t dims[2]    = {(cuuint64_t)RK, (cuuint64_t)E};
        cuuint64_t strides[1] = {(cuuint64_t)RK * 4};
        cuuint32_t box[2]     = {32, TILE};
        cuuint32_t estr[2]    = {1, 1};
        enc(&tmap, CU_TENSOR_MAP_DATA_TYPE_FLOAT32, 2, (void*)rbf,
            dims, strides, box, estr,
            CU_TENSOR_MAP_INTERLEAVE_NONE, CU_TENSOR_MAP_SWIZZLE_128B,
            CU_TENSOR_MAP_L2_PROMOTION_L2_128B, CU_TENSOR_MAP_FLOAT_OOB_FILL_NONE);
    }

    cudaFuncSetAttribute(edge_kernel, cudaFuncAttributeMaxDynamicSharedMemorySize,
                         SMEM_FLOATS * 4);
    cudaFuncSetAttribute(node_post_kernel, cudaFuncAttributeMaxDynamicSharedMemorySize,
                         65536);

    detect_idx_kernel<<<1, 32>>>((const int*)ei);
    prep_frag_kernel<<<(10 * 4 * 4 * 32 + 255) / 256, 256>>>(fw1, fw2);
    node_pre_kernel<<<NB, 256>>>(x, l1w, l1b, N);
    edge_kernel<<<NT, 256, SMEM_FLOATS * 4>>>(tmap, ei, dist, cutoff, fb1, fb2, E);
    node_post_kernel<<<NB, 256, 65536>>>(x, l2w, l2b, l3w, l3b, (float*)d_out, N);
}

// round 12
// speedup vs baseline: 1.0627x; 1.0512x over previous
#include <cuda_runtime.h>
#include <cuda.h>
#include <cstdint>

#define NMAX 50000
#define RK 300
#define TILE 128

__device__ float g_h[NMAX * 64];
__device__ float g_agg[NMAX * 64];
// fw1 frags: [c][s][pp][hn][lane] -> (b0_tl,b1_tl,b0_tl1,b1_tl1), tl=2pp(+1), half hn
__device__ float4 g_fw1q[10 * 4 * 2 * 2 * 32];
__device__ float4 g_fw2q[8 * 2 * 2 * 32];
__device__ int g_is64;

__device__ __forceinline__ float sspf(float x) {
    float t = __expf(-fabsf(x));
    return fmaxf(x, 0.f) + __logf(1.f + t) - 0.69314718055994531f;
}
__device__ __forceinline__ uint32_t cvt_tf32(float x) {
    uint32_t r; asm("cvt.rna.tf32.f32 %0, %1;" : "=r"(r) : "f"(x)); return r;
}
__device__ __forceinline__ float tf32r(float x) { return __uint_as_float(cvt_tf32(x)); }

__device__ __forceinline__ void mma_tf32(float d[4], uint32_t a0, uint32_t a1,
                                         uint32_t a2, uint32_t a3,
                                         uint32_t b0, uint32_t b1) {
    asm volatile(
        "mma.sync.aligned.m16n8k8.row.col.f32.tf32.tf32.f32 "
        "{%0,%1,%2,%3}, {%4,%5,%6,%7}, {%8,%9}, {%0,%1,%2,%3};"
        : "+f"(d[0]), "+f"(d[1]), "+f"(d[2]), "+f"(d[3])
        : "r"(a0), "r"(a1), "r"(a2), "r"(a3), "r"(b0), "r"(b1));
}
__device__ __forceinline__ void cp16(uint32_t saddr, const void* g, int sz) {
    asm volatile("cp.async.cg.shared.global [%0], [%1], 16, %2;"
                 :: "r"(saddr), "l"(g), "r"(sz));
}
__device__ __forceinline__ void cp_commit() { asm volatile("cp.async.commit_group;"); }
__device__ __forceinline__ void cp_wait0()  { asm volatile("cp.async.wait_group 0;"); }

__device__ __forceinline__ void bulk_g2s(uint32_t dst, const void* src, int bytes,
                                         uint32_t mbar) {
    asm volatile(
        "cp.async.bulk.shared::cta.global.mbarrier::complete_tx::bytes [%0], [%1], %2, [%3];"
        :: "r"(dst), "l"(src), "r"(bytes), "r"(mbar) : "memory");
}
__device__ __forceinline__ void mbar_init(uint32_t a, uint32_t cnt) {
    asm volatile("mbarrier.init.shared.b64 [%0], %1;" :: "r"(a), "r"(cnt) : "memory");
}
__device__ __forceinline__ void mbar_expect(uint32_t a, uint32_t tx) {
    asm volatile("mbarrier.arrive.expect_tx.shared.b64 _, [%0], %1;"
                 :: "r"(a), "r"(tx) : "memory");
}
__device__ __forceinline__ void mbar_wait(uint32_t a, uint32_t ph) {
    uint32_t done = 0;
    do {
        asm volatile(
            "{\n\t.reg .pred p;\n\t"
            "mbarrier.try_wait.parity.acquire.cta.shared::cta.b64 p, [%1], %2, 0x989680;\n\t"
            "selp.b32 %0, 1, 0, p;\n\t}"
            : "=r"(done) : "r"(a), "r"(ph) : "memory");
    } while (!done);
}

__global__ void detect_idx_kernel(const int* __restrict__ ei32) {
    if (threadIdx.x == 0 && blockIdx.x == 0) {
        int ornz = 0;
#pragma unroll
        for (int i = 0; i < 64; ++i) ornz |= ei32[2 * i + 1];
        g_is64 = (ornz == 0) ? 1 : 0;
    }
}

// fragment-major tf32 weights, half-split (hn) and tile-paired (pp).
__global__ void prep_frag_kernel(const float* __restrict__ fw1,
                                 const float* __restrict__ fw2) {
    int i = blockIdx.x * blockDim.x + threadIdx.x;
    if (i < 10 * 4 * 2 * 2 * 32) {
        int lane = i & 31, hn = (i >> 5) & 1, pp = (i >> 6) & 1;
        int s = (i >> 7) & 3, c = i >> 9;
        int t4 = lane & 3, g4 = lane >> 2;
        int k = c * 32 + 8 * s + t4;
        int n0 = 32 * hn + 16 * pp + g4, n1 = n0 + 8;
        float4 q;
        q.x = (k < RK) ? tf32r(fw1[k * 64 + n0]) : 0.f;
        q.y = (k + 4 < RK) ? tf32r(fw1[(k + 4) * 64 + n0]) : 0.f;
        q.z = (k < RK) ? tf32r(fw1[k * 64 + n1]) : 0.f;
        q.w = (k + 4 < RK) ? tf32r(fw1[(k + 4) * 64 + n1]) : 0.f;
        g_fw1q[i] = q;
    }
    if (i < 8 * 2 * 2 * 32) {
        int lane = i & 31, hn = (i >> 5) & 1, pp = (i >> 6) & 1, s = i >> 7;
        int t4 = lane & 3, g4 = lane >> 2;
        int k = 8 * s + t4;
        int n0 = 32 * hn + 16 * pp + g4, n1 = n0 + 8;
        float4 q;
        q.x = tf32r(fw2[k * 64 + n0]);
        q.y = tf32r(fw2[(k + 4) * 64 + n0]);
        q.z = tf32r(fw2[k * 64 + n1]);
        q.w = tf32r(fw2[(k + 4) * 64 + n1]);
        g_fw2q[i] = q;
    }
}

// ---------------------------------------------------------------------------
// node kernels (proven R6 versions)
// ---------------------------------------------------------------------------
__global__ void __launch_bounds__(256)
node_pre_kernel(const float* __restrict__ x, const float* __restrict__ W,
                const float* __restrict__ b, int N) {
    __shared__ float xs[128 * 64];
    int tid = threadIdx.x;
    int j = tid & 63, q = tid >> 6;
    long n0 = (long)blockIdx.x * 128;
    uint32_t sb = (uint32_t)__cvta_generic_to_shared(xs);
    for (int i = tid; i < 2048; i += 256) {
        long node = n0 + (i >> 4);
        cp16(sb + i * 16, x + node * 64 + (i & 15) * 4, node < N ? 16 : 0);
    }
    cp_commit();
    float Wc[64];
#pragma unroll
    for (int k = 0; k < 64; ++k) Wc[k] = W[k * 64 + j];
    float bj = b[j];
    cp_wait0();
    __syncthreads();
#pragma unroll 4
    for (int nn = 0; nn < 32; ++nn) {
        int r = nn * 4 + q;
        long node = n0 + r;
        float acc = bj;
        const float* xr = xs + r * 64;
#pragma unroll
        for (int k = 0; k < 64; k += 4) {
            float4 xv = *(const float4*)(xr + k);
            acc += xv.x * Wc[k] + xv.y * Wc[k + 1] + xv.z * Wc[k + 2] + xv.w * Wc[k + 3];
        }
        if (node < N) {
            g_h[node * 64 + j] = acc;
            g_agg[node * 64 + j] = 0.f;
        }
    }
}

__global__ void __launch_bounds__(256)
node_post_kernel(const float* __restrict__ x0, const float* __restrict__ W2,
                 const float* __restrict__ b2, const float* __restrict__ W3,
                 const float* __restrict__ b3, float* __restrict__ out, int N) {
    extern __shared__ float smp[];
    float* xs = smp;
    float* ts = smp + 8192;
    int tid = threadIdx.x;
    int j = tid & 63, q = tid >> 6;
    long n0 = (long)blockIdx.x * 128;
    uint32_t sb = (uint32_t)__cvta_generic_to_shared(xs);
    for (int i = tid; i < 2048; i += 256) {
        long node = n0 + (i >> 4);
        cp16(sb + i * 16, g_agg + node * 64 + (i & 15) * 4, node < N ? 16 : 0);
    }
    cp_commit();
    float W2c[64], W3c[64];
#pragma unroll
    for (int k = 0; k < 64; ++k) { W2c[k] = W2[k * 64 + j]; W3c[k] = W3[k * 64 + j]; }
    float b2j = b2[j], b3j = b3[j];
    cp_wait0();
    __syncthreads();
#pragma unroll 4
    for (int nn = 0; nn < 32; ++nn) {
        int r = nn * 4 + q;
        float acc = b2j;
        const float* xr = xs + r * 64;
#pragma unroll
        for (int k = 0; k < 64; k += 4) {
            float4 xv = *(const float4*)(xr + k);
            acc += xv.x * W2c[k] + xv.y * W2c[k + 1] + xv.z * W2c[k + 2] + xv.w * W2c[k + 3];
        }
        ts[r * 64 + j] = sspf(acc);
    }
    __syncthreads();
#pragma unroll 4
    for (int nn = 0; nn < 32; ++nn) {
        int r = nn * 4 + q;
        long node = n0 + r;
        float acc = b3j;
        const float* tr = ts + r * 64;
#pragma unroll
        for (int k = 0; k < 64; k += 4) {
            float4 tv = *(const float4*)(tr + k);
            acc += tv.x * W3c[k] + tv.y * W3c[k + 1] + tv.z * W3c[k + 2] + tv.w * W3c[k + 3];
        }
        if (node < N) out[node * 64 + j] = acc + x0[node * 64 + j];
    }
}

// ---------------------------------------------------------------------------
// edge kernel: SEQUENTIAL bulk loads (whole contiguous 150KB rbf tile),
// natural 300-float row stride (conflict-free LDS), 16 warps (warp pairs
// split N), one mbar wait per warp per tile, persistent CTAs.
// ---------------------------------------------------------------------------
#define OFF_A   0        // 128 rows x 300 floats = 38400 (150KB)
#define OFF_PAD 38400    // 32 floats zero pad (k-tail overreads land here)
#define OFF_C   38432    // 128 x 64 = 8192 (32KB)
#define OFF_B1  46624
#define OFF_B2  46688
#define OFF_MB  46752    // 2 mbarriers
#define SMEM_FLOATS 46756
#define CSW(r, c) ((r) * 64 + ((c) ^ (((r) & 7) << 2)))
#define FU(x) __float_as_uint(x)

__global__ void __launch_bounds__(512, 1)
edge_kernel(const float* __restrict__ rbf, const void* __restrict__ ei,
            const float* __restrict__ dist, const float* __restrict__ cutoff,
            const float* __restrict__ fb1, const float* __restrict__ fb2,
            int E, int NT, int GRIDSZ) {
    extern __shared__ __align__(1024) float sm[];
    uint32_t sbase = (uint32_t)__cvta_generic_to_shared(sm);
    int tid = threadIdx.x, lane = tid & 31, warp = tid >> 5;
    int t4 = lane & 3, g4 = lane >> 2;
    int hn = warp & 1, rw = (warp >> 1) * 16;
    uint32_t mb0 = sbase + OFF_MB * 4, mb1 = mb0 + 8;
    uint32_t mymb = (rw >= 64) ? mb1 : mb0;

    // zero A + pad once (NaN-proof), load biases, init mbarriers
    for (int i = tid; i < 38432; i += 512) sm[i] = 0.f;
    if (tid < 64) { sm[OFF_B1 + tid] = fb1[tid]; sm[OFF_B2 + tid] = fb2[tid]; }
    if (tid == 0) { mbar_init(mb0, 1); mbar_init(mb1, 1); }
    __syncthreads();

    int is64 = g_is64;
    float picf = 3.14159265f / (*cutoff);

    auto issue = [&](long t) {
        if (t >= (long)NT) return;
        long e0 = t * TILE;
        int V = (int)((long)E - e0 < TILE ? (long)E - e0 : TILE);
        int V0 = V < 64 ? V : 64;
        int V1 = V - V0;
        mbar_expect(mb0, (uint32_t)(V0 * 1200));
        bulk_g2s(sbase + OFF_A * 4, rbf + e0 * 300, V0 * 1200, mb0);
        mbar_expect(mb1, (uint32_t)(V1 * 1200));
        if (V1 > 0)
            bulk_g2s(sbase + (OFF_A + 64 * 300) * 4, rbf + (e0 + 64) * 300,
                     V1 * 1200, mb1);
    };
    if (tid == 0) issue(blockIdx.x);
    int ph = 0;

    int el = tid >> 2, qr = tid & 3;

    for (long tile = blockIdx.x; tile < (long)NT; tile += GRIDSZ) {
        long e0 = tile * TILE;

        // epilogue index/dist preload (overlaps the bulk-load wait)
        long e = e0 + el;
        long long dstn = 0, srcn = 0;
        float f = 0.f;
        if (e < (long)E) {
            if (is64) {
                const long long* pp = (const long long*)ei;
                dstn = pp[e]; srcn = pp[(long)E + e];
            } else {
                const int* pp = (const int*)ei;
                dstn = pp[e]; srcn = pp[(long)E + e];
            }
            dstn = dstn < 0 ? 0 : (dstn >= NMAX ? NMAX - 1 : dstn);
            srcn = srcn < 0 ? 0 : (srcn >= NMAX ? NMAX - 1 : srcn);
            f = 1.f + __cosf(picf * dist[e]);
        }

        // ---- GEMM1: K fully resident, single wait, 40 fused k-steps ----
        mbar_wait(mymb, ph);
        float acc[4][4];
#pragma unroll
        for (int t = 0; t < 4; ++t)
#pragma unroll
            for (int jj = 0; jj < 4; ++jj) acc[t][jj] = 0.f;

        const float* A0 = sm + OFF_A + (rw + g4) * 300 + t4;
        const float* A1 = A0 + 8 * 300;
        const float4* B1 = g_fw1q + hn * 32 + lane;
        float4 qa0 = __ldg(B1), qa1 = __ldg(B1 + 64);
#pragma unroll 4
        for (int cs = 0; cs < 40; ++cs) {
            float4 qb0, qb1;
            if (cs < 39) {
                qb0 = __ldg(B1 + (cs + 1) * 128);
                qb1 = __ldg(B1 + (cs + 1) * 128 + 64);
            }
            uint32_t a0 = FU(A0[8 * cs]);
            uint32_t a1 = FU(A1[8 * cs]);
            uint32_t a2 = FU(A0[8 * cs + 4]);
            uint32_t a3 = FU(A1[8 * cs + 4]);
            mma_tf32(acc[0], a0, a1, a2, a3, FU(qa0.x), FU(qa0.y));
            mma_tf32(acc[1], a0, a1, a2, a3, FU(qa0.z), FU(qa0.w));
            mma_tf32(acc[2], a0, a1, a2, a3, FU(qa1.x), FU(qa1.y));
            mma_tf32(acc[3], a0, a1, a2, a3, FU(qa1.z), FU(qa1.w));
            qa0 = qb0; qa1 = qb1;
        }

        // bias + ssp -> stage C1 (swizzled)
#pragma unroll
        for (int tl = 0; tl < 4; ++tl) {
            int cb = 32 * hn + 8 * tl + 2 * t4;
            float b0v = sm[OFF_B1 + cb], b1v = sm[OFF_B1 + cb + 1];
            *(float2*)&sm[OFF_C + CSW(rw + g4, cb)] =
                make_float2(sspf(acc[tl][0] + b0v), sspf(acc[tl][1] + b1v));
            *(float2*)&sm[OFF_C + CSW(rw + g4 + 8, cb)] =
                make_float2(sspf(acc[tl][2] + b0v), sspf(acc[tl][3] + b1v));
        }
        __syncthreads();                      // (1) C1 complete; A consumed

        if (tid == 0) issue(tile + GRIDSZ);   // next tile's sequential bulks

        // ---- GEMM2: read A-frags (full K=64) from C1 ----
        float af[8][4];
#pragma unroll
        for (int s = 0; s < 8; ++s) {
            int col = 8 * s + t4;
            af[s][0] = sm[OFF_C + CSW(rw + g4, col)];
            af[s][1] = sm[OFF_C + CSW(rw + g4 + 8, col)];
            af[s][2] = sm[OFF_C + CSW(rw + g4, col + 4)];
            af[s][3] = sm[OFF_C + CSW(rw + g4 + 8, col + 4)];
        }
        __syncthreads();                      // (2) reads done before overwrite

        float acc2[4][4];
#pragma unroll
        for (int t = 0; t < 4; ++t)
#pragma unroll
            for (int jj = 0; jj < 4; ++jj) acc2[t][jj] = 0.f;
        const float4* B2 = g_fw2q + hn * 32 + lane;
#pragma unroll
        for (int s = 0; s < 8; ++s) {
            float4 q0 = __ldg(B2 + s * 128), q1 = __ldg(B2 + s * 128 + 64);
            uint32_t a0 = FU(af[s][0]), a1 = FU(af[s][1]);
            uint32_t a2 = FU(af[s][2]), a3 = FU(af[s][3]);
            mma_tf32(acc2[0], a0, a1, a2, a3, FU(q0.x), FU(q0.y));
            mma_tf32(acc2[1], a0, a1, a2, a3, FU(q0.z), FU(q0.w));
            mma_tf32(acc2[2], a0, a1, a2, a3, FU(q1.x), FU(q1.y));
            mma_tf32(acc2[3], a0, a1, a2, a3, FU(q1.z), FU(q1.w));
        }

        // bias + ssp -> w2 into C
#pragma unroll
        for (int tl = 0; tl < 4; ++tl) {
            int cb = 32 * hn + 8 * tl + 2 * t4;
            float b0v = sm[OFF_B2 + cb], b1v = sm[OFF_B2 + cb + 1];
            *(float2*)&sm[OFF_C + CSW(rw + g4, cb)] =
                make_float2(sspf(acc2[tl][0] + b0v), sspf(acc2[tl][1] + b1v));
            *(float2*)&sm[OFF_C + CSW(rw + g4 + 8, cb)] =
                make_float2(sspf(acc2[tl][2] + b0v), sspf(acc2[tl][3] + b1v));
        }
        __syncthreads();                      // (3) w2 ready

        // epilogue: gather h[src], scatter atomics into agg[dst]
        if (e < (long)E) {
            const float* hrow = g_h + (long)srcn * 64 + qr * 16;
            float* arow = g_agg + (long)dstn * 64 + qr * 16;
#pragma unroll
            for (int jj = 0; jj < 4; ++jj) {
                float4 w = *(const float4*)&sm[OFF_C + CSW(el, qr * 16 + 4 * jj)];
                float4 h4 = *(const float4*)(hrow + 4 * jj);
                atomicAdd((float4*)(arow + 4 * jj),
                          make_float4(w.x * h4.x * f, w.y * h4.y * f,
                                      w.z * h4.z * f, w.w * h4.w * f));
            }
        }
        __syncthreads();                      // (4) C free for next staging
        ph ^= 1;
    }
}

// ---------------------------------------------------------------------------
extern "C" void kernel_launch(void* const* d_in, const int* in_sizes, int n_in,
                              void* d_out, int out_size) {
    const void* ei       = d_in[0];
    const float* x       = (const float*)d_in[1];
    const float* rbf     = (const float*)d_in[2];
    const float* dist    = (const float*)d_in[3];
    const float* cutoff  = (const float*)d_in[4];
    const float* fw1     = (const float*)d_in[5];
    const float* fb1     = (const float*)d_in[6];
    const float* fw2     = (const float*)d_in[7];
    const float* fb2     = (const float*)d_in[8];
    const float* l1w     = (const float*)d_in[9];
    const float* l1b     = (const float*)d_in[10];
    const float* l2w     = (const float*)d_in[11];
    const float* l2b     = (const float*)d_in[12];
    const float* l3w     = (const float*)d_in[13];
    const float* l3b     = (const float*)d_in[14];

    int E = in_sizes[0] / 2;
    int N = in_sizes[1] / 64;
    int NT = (E + TILE - 1) / TILE;
    int NB = (N + 127) / 128;

    static int sms = 0;
    if (!sms) cudaDeviceGetAttribute(&sms, cudaDevAttrMultiProcessorCount, 0);
    int grid = sms > 0 ? sms : 148;
    if (grid > NT) grid = NT;

    cudaFuncSetAttribute(edge_kernel, cudaFuncAttributeMaxDynamicSharedMemorySize,
                         SMEM_FLOATS * 4);
    cudaFuncSetAttribute(node_post_kernel, cudaFuncAttributeMaxDynamicSharedMemorySize,
                         65536);

    detect_idx_kernel<<<1, 32>>>((const int*)ei);
    prep_frag_kernel<<<(10 * 4 * 2 * 2 * 32 + 255) / 256, 256>>>(fw1, fw2);
    node_pre_kernel<<<NB, 256>>>(x, l1w, l1b, N);
    edge_kernel<<<grid, 512, SMEM_FLOATS * 4>>>(rbf, ei, dist, cutoff,
                                                fb1, fb2, E, NT, grid);
    node_post_kernel<<<NB, 256, 65536>>>(x, l2w, l2b, l3w, l3b, (float*)d_out, N);
}